// round 1
// baseline (speedup 1.0000x reference)
#include <cuda_runtime.h>
#include <math.h>

// ---------------- problem constants ----------------
#define Bsz   8
#define Hh    128
#define Wd    128
#define Cc    192
#define NHh   6
#define HD    32          // head dim
#define LL    (Hh*Wd)     // 16384
#define TOK   (Bsz*LL)    // 131072
#define HDIMc 384
#define REDc  24

// ---------------- scratch (device globals, no allocation) ----------------
__device__ float g_n1  [(size_t)TOK*Cc];    // LN1 output, later reused as n2
__device__ float g_attn[(size_t)TOK*Cc];    // window-attention output
__device__ float g_conv[(size_t)TOK*Cc];    // gelu(dwconv(n1))
__device__ float g_h   [(size_t)TOK*HDIMc]; // gelu(n2 @ fc1)
__device__ float g_h2  [(size_t)TOK*HDIMc]; // dwconv(h)
__device__ float g_poolp[Bsz*128*Cc];       // partial pooling sums (deterministic)
__device__ float g_cm  [Bsz*Cc];            // channel gate

__device__ __forceinline__ float gelu_f(float x){
    return 0.5f*x*(1.f + erff(x*0.70710678118654752f));
}

// ---------------- LayerNorm1: one warp per token ----------------
__global__ void ln_kernel(const float* __restrict__ x, const float* __restrict__ w,
                          const float* __restrict__ b, float* __restrict__ out){
    int warp = (blockIdx.x*blockDim.x + threadIdx.x) >> 5;
    int lane = threadIdx.x & 31;
    if (warp >= TOK) return;
    const float* xp = x + (size_t)warp*Cc;
    float v[6]; float s = 0.f;
#pragma unroll
    for (int k=0;k<6;k++){ v[k] = xp[lane+32*k]; s += v[k]; }
#pragma unroll
    for (int o=16;o;o>>=1) s += __shfl_xor_sync(0xffffffffu, s, o);
    float mean = s*(1.f/192.f);
    float q = 0.f;
#pragma unroll
    for (int k=0;k<6;k++){ float d=v[k]-mean; q += d*d; }
#pragma unroll
    for (int o=16;o;o>>=1) q += __shfl_xor_sync(0xffffffffu, q, o);
    float inv = rsqrtf(q*(1.f/192.f)+1e-5f);
    float* op = out + (size_t)warp*Cc;
#pragma unroll
    for (int k=0;k<6;k++){ int c=lane+32*k; op[c] = (v[k]-mean)*inv*w[c]+b[c]; }
}

// ---------------- fused window attention: 1 block per 8x8 window ----------------
#define XS 196   // padded row stride for 192-ch smem tiles (bank-conflict free)
#define QS 36    // padded row stride for 32-float q/k/v rows
#define LS 68    // padded row stride for 64-float logit rows
#define ATTN_SMEM ((64*XS*2 + 64*QS*3 + 64*LS)*4)

__global__ __launch_bounds__(512,1) void attn_kernel(
    const float* __restrict__ n1, const float* __restrict__ qkv_w,
    const float* __restrict__ proj_w, const float* __restrict__ proj_b,
    const float* __restrict__ bias, float* __restrict__ out)
{
    extern __shared__ float sm[];
    float* xw  = sm;              // [64][XS]   window tokens (192 ch)
    float* osm = xw  + 64*XS;     // [64][XS]   per-head concat output
    float* qsm = osm + 64*XS;     // [64][QS]
    float* ksm = qsm + 64*QS;
    float* vsm = ksm + 64*QS;
    float* lsm = vsm + 64*QS;     // [64][LS]   logits / attn probs

    const int wdx = blockIdx.x;
    const int b = wdx >> 8, wh = (wdx>>4)&15, wwi = wdx&15;
    const int tid = threadIdx.x;

    // load window tokens (float4), zero output accumulator
    for (int s = tid; s < 64*48; s += 512){
        int t = s/48, c4 = (s - t*48)*4;
        int l = (wh*8 + (t>>3))*Wd + (wwi*8 + (t&7));
        *(float4*)&xw[t*XS + c4] = *(const float4*)&n1[((size_t)b*LL + l)*Cc + c4];
    }
    for (int s = tid; s < 64*XS; s += 512) osm[s] = 0.f;
    __syncthreads();

    const int i = tid >> 3;   // token 0..63
    const int g = tid & 7;    // 0..7

    for (int h = 0; h < NHh; h++){
        // ---- q,k,v for this head: each thread computes 4 outputs of each ----
        {
            float aq0=0,aq1=0,aq2=0,aq3=0;
            float ak0=0,ak1=0,ak2=0,ak3=0;
            float av0=0,av1=0,av2=0,av3=0;
            const float* wp = qkv_w + h*HD + g*4;
            const float* xr = xw + i*XS;
            for (int k=0;k<Cc;k++){
                float a = xr[k];
                const float* wr = wp + k*(3*Cc);
                float4 q4 = *(const float4*)wr;
                float4 k4 = *(const float4*)(wr+Cc);
                float4 v4 = *(const float4*)(wr+2*Cc);
                aq0 += a*q4.x; aq1 += a*q4.y; aq2 += a*q4.z; aq3 += a*q4.w;
                ak0 += a*k4.x; ak1 += a*k4.y; ak2 += a*k4.z; ak3 += a*k4.w;
                av0 += a*v4.x; av1 += a*v4.y; av2 += a*v4.z; av3 += a*v4.w;
            }
            int o = i*QS + g*4;
            qsm[o]=aq0; qsm[o+1]=aq1; qsm[o+2]=aq2; qsm[o+3]=aq3;
            ksm[o]=ak0; ksm[o+1]=ak1; ksm[o+2]=ak2; ksm[o+3]=ak3;
            vsm[o]=av0; vsm[o+1]=av1; vsm[o+2]=av2; vsm[o+3]=av3;
        }
        __syncthreads();
        // ---- logits: thread computes 8 cols of its row ----
        {
            float qr[32];
#pragma unroll
            for (int d=0; d<32; d+=4){
                float4 t4 = *(const float4*)&qsm[i*QS+d];
                qr[d]=t4.x; qr[d+1]=t4.y; qr[d+2]=t4.z; qr[d+3]=t4.w;
            }
            const float* bp = bias + ((size_t)h*64 + i)*64;
#pragma unroll
            for (int jj=0;jj<8;jj++){
                int j = g*8+jj;
                float s=0.f;
#pragma unroll
                for (int d=0; d<32; d+=4){
                    float4 k4 = *(const float4*)&ksm[j*QS+d];
                    s += qr[d]*k4.x + qr[d+1]*k4.y + qr[d+2]*k4.z + qr[d+3]*k4.w;
                }
                lsm[i*LS + j] = s*0.17677669529663687f + bp[j];
            }
        }
        __syncthreads();
        // ---- softmax: one thread per row ----
        if (tid < 64){
            float* row = lsm + tid*LS;
            float m = row[0];
            for (int j=1;j<64;j++) m = fmaxf(m,row[j]);
            float s=0.f;
            for (int j=0;j<64;j++){ float e=__expf(row[j]-m); row[j]=e; s+=e; }
            float inv=1.f/s;
            for (int j=0;j<64;j++) row[j]*=inv;
        }
        __syncthreads();
        // ---- out_h = attn @ v, write into channel slice h*32.. ----
        {
            float a0=0,a1=0,a2=0,a3=0;
            const float* lr = lsm + i*LS;
            for (int j=0;j<64;j++){
                float a = lr[j];
                float4 v4 = *(const float4*)&vsm[j*QS + g*4];
                a0+=a*v4.x; a1+=a*v4.y; a2+=a*v4.z; a3+=a*v4.w;
            }
            float* op = &osm[i*XS + h*HD + g*4];
            op[0]=a0; op[1]=a1; op[2]=a2; op[3]=a3;
        }
        __syncthreads();
    }
    // ---- proj: out @ proj_w + proj_b, scatter back to [B,L,C] ----
    {
        int l = (wh*8 + (i>>3))*Wd + (wwi*8 + (i&7));
        float* outp = out + ((size_t)b*LL + l)*Cc;
        const float* orow = osm + i*XS;
#pragma unroll
        for (int chunk=0; chunk<6; chunk++){
            int c0 = chunk*32 + g*4;
            float a0=0,a1=0,a2=0,a3=0;
            for (int k=0;k<Cc;k++){
                float a = orow[k];
                float4 w4 = *(const float4*)&proj_w[k*Cc + c0];
                a0+=a*w4.x; a1+=a*w4.y; a2+=a*w4.z; a3+=a*w4.w;
            }
            float4 pb = *(const float4*)&proj_b[c0];
            float4 r; r.x=a0+pb.x; r.y=a1+pb.y; r.z=a2+pb.z; r.w=a3+pb.w;
            *(float4*)&outp[c0] = r;
        }
    }
}

// ---------------- depthwise 3x3 'SAME' conv, channel-last ----------------
__global__ void dwconv_kernel(const float* __restrict__ in, const float* __restrict__ w,
                              float* __restrict__ out, int C, int doGelu){
    long long g = (long long)blockIdx.x*blockDim.x + threadIdx.x;
    long long total = (long long)TOK*C;
    if (g >= total) return;
    int c  = (int)(g % C);
    long long s = g / C;
    int xx = (int)(s % Wd);
    int yy = (int)((s / Wd) % Hh);
    int b  = (int)(s / LL);
    const float* wp = w + c*9;
    float acc = 0.f;
#pragma unroll
    for (int ky=0; ky<3; ky++){
        int iy = yy + ky - 1;
        if ((unsigned)iy >= (unsigned)Hh) continue;
#pragma unroll
        for (int kx=0; kx<3; kx++){
            int ix = xx + kx - 1;
            if ((unsigned)ix >= (unsigned)Wd) continue;
            acc += in[((size_t)b*LL + (size_t)iy*Wd + ix)*C + c] * wp[ky*3+kx];
        }
    }
    if (doGelu) acc = gelu_f(acc);
    out[g] = acc;
}

// ---------------- deterministic pooling (two stages, no atomics) ----------------
__global__ void pool_partial(const float* __restrict__ conv, float* __restrict__ pp){
    int b = blockIdx.y, chunk = blockIdx.x, c = threadIdx.x;  // 128 chunks x 192 thr
    const float* p = conv + ((size_t)b*LL + (size_t)chunk*128)*Cc + c;
    float s=0.f;
    for (int r=0;r<128;r++) s += p[(size_t)r*Cc];
    pp[(b*128+chunk)*Cc + c] = s;
}

__global__ void pool_final_cm(const float* __restrict__ pp, const float* __restrict__ w1,
                              const float* __restrict__ w2, float* __restrict__ cm){
    int b = blockIdx.x, c = threadIdx.x; // 192 threads
    __shared__ float ps[Cc];
    __shared__ float ts[REDc];
    float s=0.f;
    for (int r=0;r<128;r++) s += pp[(b*128+r)*Cc + c];
    ps[c] = s*(1.f/(float)LL);
    __syncthreads();
    if (c < REDc){
        float t=0.f;
        for (int j=0;j<Cc;j++) t += ps[j]*w1[c*Cc+j];
        ts[c] = gelu_f(t);
    }
    __syncthreads();
    float a=0.f;
#pragma unroll
    for (int r=0;r<REDc;r++) a += ts[r]*w2[c*REDc+r];
    cm[b*Cc+c] = 1.f/(1.f+__expf(-a));
}

// ---------------- residual + LN2 fused: one warp per token ----------------
__global__ void resid_ln2_kernel(const float* __restrict__ x, const float* __restrict__ attn,
    const float* __restrict__ conv, const float* __restrict__ cm,
    const float* __restrict__ w, const float* __restrict__ bb,
    float* __restrict__ xmid, float* __restrict__ n2){
    int warp = (blockIdx.x*blockDim.x + threadIdx.x) >> 5;
    int lane = threadIdx.x & 31;
    if (warp >= TOK) return;
    int b = warp / LL;
    size_t base = (size_t)warp*Cc;
    float v[6]; float s=0.f;
#pragma unroll
    for (int k=0;k<6;k++){
        int c = lane+32*k;
        float xm = x[base+c] + attn[base+c]*cm[b*Cc+c] + conv[base+c];
        xmid[base+c] = xm;
        v[k]=xm; s+=xm;
    }
#pragma unroll
    for (int o=16;o;o>>=1) s += __shfl_xor_sync(0xffffffffu, s, o);
    float mean = s*(1.f/192.f);
    float q = 0.f;
#pragma unroll
    for (int k=0;k<6;k++){ float d=v[k]-mean; q += d*d; }
#pragma unroll
    for (int o=16;o;o>>=1) q += __shfl_xor_sync(0xffffffffu, q, o);
    float inv = rsqrtf(q*(1.f/192.f)+1e-5f);
#pragma unroll
    for (int k=0;k<6;k++){ int c=lane+32*k; n2[base+c] = (v[k]-mean)*inv*w[c]+bb[c]; }
}

// ---------------- tiled fp32 GEMM: C = A[M,K] @ B[K,N], epilogue gelu or +res ----------------
__global__ __launch_bounds__(256) void gemm64(
    const float* __restrict__ A, const float* __restrict__ B,
    float* __restrict__ C, const float* __restrict__ res,
    int N, int K, int mode)
{
    __shared__ float As[64][36];
    __shared__ float Bs[32][68];
    const int tx = threadIdx.x & 15, ty = threadIdx.x >> 4;
    const int m0 = blockIdx.y*64, n0 = blockIdx.x*64;
    float acc[4][4] = {};
    for (int k0 = 0; k0 < K; k0 += 32){
#pragma unroll
        for (int it=0; it<2; it++){
            int slot = threadIdx.x + it*256;
            int r  = slot >> 3, c4 = (slot & 7)*4;
            *(float4*)&As[r][c4] = *(const float4*)&A[(size_t)(m0+r)*K + k0 + c4];
            int kk = slot >> 4, n4 = (slot & 15)*4;
            *(float4*)&Bs[kk][n4] = *(const float4*)&B[(size_t)(k0+kk)*N + n0 + n4];
        }
        __syncthreads();
#pragma unroll
        for (int kk=0; kk<32; kk++){
            float4 b4 = *(const float4*)&Bs[kk][tx*4];
            float a0 = As[ty*4+0][kk], a1 = As[ty*4+1][kk];
            float a2 = As[ty*4+2][kk], a3 = As[ty*4+3][kk];
            acc[0][0]+=a0*b4.x; acc[0][1]+=a0*b4.y; acc[0][2]+=a0*b4.z; acc[0][3]+=a0*b4.w;
            acc[1][0]+=a1*b4.x; acc[1][1]+=a1*b4.y; acc[1][2]+=a1*b4.z; acc[1][3]+=a1*b4.w;
            acc[2][0]+=a2*b4.x; acc[2][1]+=a2*b4.y; acc[2][2]+=a2*b4.z; acc[2][3]+=a2*b4.w;
            acc[3][0]+=a3*b4.x; acc[3][1]+=a3*b4.y; acc[3][2]+=a3*b4.z; acc[3][3]+=a3*b4.w;
        }
        __syncthreads();
    }
#pragma unroll
    for (int r=0;r<4;r++){
        int m = m0 + ty*4 + r;
        size_t o = (size_t)m*N + n0 + tx*4;
        float4 v; v.x=acc[r][0]; v.y=acc[r][1]; v.z=acc[r][2]; v.w=acc[r][3];
        if (mode==0){
            v.x=gelu_f(v.x); v.y=gelu_f(v.y); v.z=gelu_f(v.z); v.w=gelu_f(v.w);
        } else {
            float4 rr = *(const float4*)&res[o];
            v.x+=rr.x; v.y+=rr.y; v.z+=rr.z; v.w+=rr.w;
        }
        *(float4*)&C[o] = v;
    }
}

// ---------------- launch ----------------
extern "C" void kernel_launch(void* const* d_in, const int* in_sizes, int n_in,
                              void* d_out, int out_size){
    const float* x     = (const float*)d_in[0];
    // d_in[1]=H, d_in[2]=W (compile-time constants here)
    const float* n1w   = (const float*)d_in[3];
    const float* n1b   = (const float*)d_in[4];
    const float* qkvw  = (const float*)d_in[5];
    const float* projw = (const float*)d_in[6];
    const float* projb = (const float*)d_in[7];
    const float* abias = (const float*)d_in[8];
    const float* convw = (const float*)d_in[9];
    const float* cgw1  = (const float*)d_in[10];
    const float* cgw2  = (const float*)d_in[11];
    const float* n2w   = (const float*)d_in[12];
    const float* n2b   = (const float*)d_in[13];
    const float* fc1w  = (const float*)d_in[14];
    const float* smixw = (const float*)d_in[15];
    const float* fc2w  = (const float*)d_in[16];
    float* out = (float*)d_out;

    float *n1p, *attnp, *convp, *hp, *h2p, *ppp, *cmp;
    cudaGetSymbolAddress((void**)&n1p,   g_n1);
    cudaGetSymbolAddress((void**)&attnp, g_attn);
    cudaGetSymbolAddress((void**)&convp, g_conv);
    cudaGetSymbolAddress((void**)&hp,    g_h);
    cudaGetSymbolAddress((void**)&h2p,   g_h2);
    cudaGetSymbolAddress((void**)&ppp,   g_poolp);
    cudaGetSymbolAddress((void**)&cmp,   g_cm);

    cudaFuncSetAttribute(attn_kernel, cudaFuncAttributeMaxDynamicSharedMemorySize, ATTN_SMEM);

    // 1. n1 = LN1(x)
    ln_kernel<<<TOK/8, 256>>>(x, n1w, n1b, n1p);
    // 2. window attention -> g_attn
    attn_kernel<<<2048, 512, ATTN_SMEM>>>(n1p, qkvw, projw, projb, abias, attnp);
    // 3. conv_feat = gelu(dwconv(n1)) -> g_conv
    dwconv_kernel<<<(TOK*Cc)/256, 256>>>(n1p, convw, convp, Cc, 1);
    // 4-5. pooled -> channel gate (deterministic two-stage)
    pool_partial<<<dim3(128, Bsz), Cc>>>(convp, ppp);
    pool_final_cm<<<Bsz, Cc>>>(ppp, cgw1, cgw2, cmp);
    // 6. xmid = x + attn*cm + conv -> d_out ; n2 = LN2(xmid) -> g_n1 (reuse)
    resid_ln2_kernel<<<TOK/8, 256>>>(x, attnp, convp, cmp, n2w, n2b, out, n1p);
    // 7. h = gelu(n2 @ fc1_w) -> g_h
    gemm64<<<dim3(HDIMc/64, TOK/64), 256>>>(n1p, fc1w, hp, nullptr, HDIMc, Cc, 0);
    // 8. h2 = dwconv(h, smix_w)
    dwconv_kernel<<<(TOK*HDIMc)/256, 256>>>(hp, smixw, h2p, HDIMc, 0);
    // 9. out = xmid + h2 @ fc2_w (in-place residual into d_out)
    gemm64<<<dim3(Cc/64, TOK/64), 256>>>(h2p, fc2w, out, out, Cc, HDIMc, 1);
}

// round 6
// speedup vs baseline: 3.5313x; 3.5313x over previous
#include <cuda_runtime.h>
#include <cstdint>
#include <math.h>

// ---------------- problem constants ----------------
#define Bsz   8
#define Hh    128
#define Wd    128
#define Cc    192
#define NHh   6
#define HD    32
#define LL    (Hh*Wd)     // 16384
#define TOK   (Bsz*LL)    // 131072
#define HDIMc 384
#define REDc  24
#define QKVN  576

// ---------------- scratch (device globals) ----------------
__device__ float g_n1  [(size_t)TOK*Cc];
__device__ float g_attn[(size_t)TOK*Cc];
__device__ float g_conv[(size_t)TOK*Cc];
__device__ float g_ao  [(size_t)TOK*Cc];
__device__ float g_h   [(size_t)TOK*HDIMc];
__device__ float g_h2  [(size_t)TOK*HDIMc];
__device__ float g_qkv [(size_t)TOK*QKVN];
__device__ float g_poolp[Bsz*128*Cc];
__device__ float g_cm  [Bsz*Cc];
__device__ float g_wt  [294912];

#define WT_QKV 0
#define WT_PROJ 110592
#define WT_FC1 147456
#define WT_FC2 221184

__device__ __forceinline__ float gelu_f(float x){
    return 0.5f*x*(1.f + erff(x*0.70710678118654752f));
}
__device__ __forceinline__ uint32_t f2tf32(float x){
    uint32_t t;
    asm("cvt.rna.tf32.f32 %0, %1;" : "=r"(t) : "f"(x));
    return t;
}

// ---------------- weight transpose (tiny) ----------------
__global__ void transpose_all(const float* __restrict__ qkvw, const float* __restrict__ projw,
                              const float* __restrict__ fc1w, const float* __restrict__ fc2w,
                              float* __restrict__ wt){
    int idx = blockIdx.x*256 + threadIdx.x;
    if (idx < 110592){
        int k = idx / QKVN, n = idx % QKVN;
        wt[WT_QKV + n*Cc + k] = qkvw[idx];
    } else if (idx < 147456){
        int l = idx - 110592; int k = l / Cc, n = l % Cc;
        wt[WT_PROJ + n*Cc + k] = projw[l];
    } else if (idx < 221184){
        int l = idx - 147456; int k = l / HDIMc, n = l % HDIMc;
        wt[WT_FC1 + n*Cc + k] = fc1w[l];
    } else if (idx < 294912){
        int l = idx - 221184; int k = l / Cc, n = l % Cc;
        wt[WT_FC2 + n*HDIMc + k] = fc2w[l];
    }
}

// ---------------- tf32 mma.sync GEMM: C[M,N] = A[M,K] @ Bt[N,K]^T ----------------
// BM=128, BN=64, BK=32; 256 threads = 8 warps (4m x 2n), warp tile 32x32.
// modes: 0 none, 1 gelu, 2 +bias(vec), 3 +residual(mat)
#define ASTR 36
#define BSTR 36

__global__ __launch_bounds__(256) void gemm_mma(
    const float* __restrict__ A, const float* __restrict__ Bt,
    float* __restrict__ Cmat, const float* __restrict__ aux,
    int N, int K, int mode)
{
    __shared__ float As[128*ASTR];
    __shared__ float Bs[64*BSTR];
    const int tid = threadIdx.x;
    const int wid = tid >> 5, lane = tid & 31;
    const int wm = wid >> 1, wn = wid & 1;
    const int lg = lane >> 2, lr = lane & 3;
    const int m0 = blockIdx.y << 7, n0 = blockIdx.x << 6;

    float acc[2][4][4] = {};

    const int ldr = tid >> 3;          // 0..31
    const int ldc = (tid & 7) * 4;     // 0,4,...,28

    const int nIter = K >> 5;
    for (int it = 0; it < nIter; ++it){
        const int k0 = it << 5;
        // ---- A tile 128x32 (tf32-converted), conflict-free stride 36 ----
        #pragma unroll
        for (int p = 0; p < 4; p++){
            int r = ldr + p*32;
            float4 v = *(const float4*)&A[(size_t)(m0 + r)*K + k0 + ldc];
            float4 t;
            t.x = __uint_as_float(f2tf32(v.x)); t.y = __uint_as_float(f2tf32(v.y));
            t.z = __uint_as_float(f2tf32(v.z)); t.w = __uint_as_float(f2tf32(v.w));
            *(float4*)&As[r*ASTR + ldc] = t;
        }
        // ---- B tile 64x32 ----
        #pragma unroll
        for (int p = 0; p < 2; p++){
            int r = ldr + p*32;
            float4 v = *(const float4*)&Bt[(size_t)(n0 + r)*K + k0 + ldc];
            float4 t;
            t.x = __uint_as_float(f2tf32(v.x)); t.y = __uint_as_float(f2tf32(v.y));
            t.z = __uint_as_float(f2tf32(v.z)); t.w = __uint_as_float(f2tf32(v.w));
            *(float4*)&Bs[r*BSTR + ldc] = t;
        }
        __syncthreads();
        #pragma unroll
        for (int ks = 0; ks < 4; ks++){
            const int kk = ks*8;
            uint32_t a[2][4], b[4][2];
            #pragma unroll
            for (int mt = 0; mt < 2; mt++){
                int rb = wm*32 + mt*16 + lg;
                a[mt][0] = __float_as_uint(As[rb*ASTR + kk + lr]);
                a[mt][1] = __float_as_uint(As[(rb+8)*ASTR + kk + lr]);
                a[mt][2] = __float_as_uint(As[rb*ASTR + kk + lr + 4]);
                a[mt][3] = __float_as_uint(As[(rb+8)*ASTR + kk + lr + 4]);
            }
            #pragma unroll
            for (int nt = 0; nt < 4; nt++){
                int nb = wn*32 + nt*8 + lg;
                b[nt][0] = __float_as_uint(Bs[nb*BSTR + kk + lr]);
                b[nt][1] = __float_as_uint(Bs[nb*BSTR + kk + lr + 4]);
            }
            #pragma unroll
            for (int mt = 0; mt < 2; mt++)
            #pragma unroll
            for (int nt = 0; nt < 4; nt++){
                asm volatile(
                    "mma.sync.aligned.m16n8k8.row.col.f32.tf32.tf32.f32 "
                    "{%0,%1,%2,%3}, {%4,%5,%6,%7}, {%8,%9}, {%0,%1,%2,%3};"
                    : "+f"(acc[mt][nt][0]), "+f"(acc[mt][nt][1]),
                      "+f"(acc[mt][nt][2]), "+f"(acc[mt][nt][3])
                    : "r"(a[mt][0]), "r"(a[mt][1]), "r"(a[mt][2]), "r"(a[mt][3]),
                      "r"(b[nt][0]), "r"(b[nt][1]));
            }
        }
        __syncthreads();
    }
    // ---- epilogue ----
    #pragma unroll
    for (int mt = 0; mt < 2; mt++){
        #pragma unroll
        for (int rr = 0; rr < 2; rr++){
            int row = m0 + wm*32 + mt*16 + lg + rr*8;
            #pragma unroll
            for (int nt = 0; nt < 4; nt++){
                int col = n0 + wn*32 + nt*8 + lr*2;
                float d0 = acc[mt][nt][rr*2], d1 = acc[mt][nt][rr*2+1];
                size_t o = (size_t)row*N + col;
                if (mode == 1){ d0 = gelu_f(d0); d1 = gelu_f(d1); }
                else if (mode == 2){ d0 += aux[col]; d1 += aux[col+1]; }
                else if (mode == 3){
                    float2 rv = *(const float2*)&aux[o];
                    d0 += rv.x; d1 += rv.y;
                }
                float2 v; v.x = d0; v.y = d1;
                *(float2*)&Cmat[o] = v;
            }
        }
    }
}

// ---------------- LayerNorm1: one warp per token ----------------
__global__ void ln_kernel(const float* __restrict__ x, const float* __restrict__ w,
                          const float* __restrict__ b, float* __restrict__ out){
    int warp = (blockIdx.x*blockDim.x + threadIdx.x) >> 5;
    int lane = threadIdx.x & 31;
    if (warp >= TOK) return;
    const float* xp = x + (size_t)warp*Cc;
    float v[6]; float s = 0.f;
#pragma unroll
    for (int k=0;k<6;k++){ v[k] = xp[lane+32*k]; s += v[k]; }
#pragma unroll
    for (int o=16;o;o>>=1) s += __shfl_xor_sync(0xffffffffu, s, o);
    float mean = s*(1.f/192.f);
    float q = 0.f;
#pragma unroll
    for (int k=0;k<6;k++){ float d=v[k]-mean; q += d*d; }
#pragma unroll
    for (int o=16;o;o>>=1) q += __shfl_xor_sync(0xffffffffu, q, o);
    float inv = rsqrtf(q*(1.f/192.f)+1e-5f);
    float* op = out + (size_t)warp*Cc;
#pragma unroll
    for (int k=0;k<6;k++){ int c=lane+32*k; op[c] = (v[k]-mean)*inv*w[c]+b[c]; }
}

// ---------------- attention core (q,k,v precomputed) ----------------
#define AQS 36
#define ALS 72
__global__ __launch_bounds__(512) void attn_core(const float* __restrict__ qkv,
        const float* __restrict__ bias, float* __restrict__ ao)
{
    __shared__ float qs[64*AQS], ks[64*AQS], vs[64*AQS], ls[64*ALS];
    const int wdx = blockIdx.x;
    const int b = wdx >> 8, wh = (wdx>>4)&15, ww = wdx&15;
    const int tid = threadIdx.x;
    const int i = tid >> 3;
    const int g = tid & 7;
    const int lrow = wh*8 + (i>>3), lcol = ww*8 + (i&7);
    const size_t tok = (size_t)b*LL + (size_t)lrow*Wd + lcol;
    const size_t qb = tok*QKVN;

    for (int h = 0; h < NHh; h++){
        if (h) __syncthreads();
        {
            int off = h*HD + g*4;
            *(float4*)&qs[i*AQS + g*4] = *(const float4*)&qkv[qb + off];
            *(float4*)&ks[i*AQS + g*4] = *(const float4*)&qkv[qb + 192 + off];
            *(float4*)&vs[i*AQS + g*4] = *(const float4*)&qkv[qb + 384 + off];
        }
        __syncthreads();
        float e[8];
        {
            float qr[32];
#pragma unroll
            for (int d=0; d<32; d+=4){
                float4 t4 = *(const float4*)&qs[i*AQS+d];
                qr[d]=t4.x; qr[d+1]=t4.y; qr[d+2]=t4.z; qr[d+3]=t4.w;
            }
            const float* bp = bias + ((size_t)h*64 + i)*64;
#pragma unroll
            for (int jj=0;jj<8;jj++){
                int j = jj*8 + g;
                float s = 0.f;
#pragma unroll
                for (int d=0; d<32; d+=4){
                    float4 k4 = *(const float4*)&ks[j*AQS+d];
                    s += qr[d]*k4.x + qr[d+1]*k4.y + qr[d+2]*k4.z + qr[d+3]*k4.w;
                }
                e[jj] = s*0.17677669529663687f + bp[j];
            }
        }
        {
            float m = e[0];
#pragma unroll
            for (int jj=1;jj<8;jj++) m = fmaxf(m, e[jj]);
#pragma unroll
            for (int o=1;o<8;o<<=1) m = fmaxf(m, __shfl_xor_sync(0xffffffffu, m, o));
            float sum = 0.f;
#pragma unroll
            for (int jj=0;jj<8;jj++){ e[jj] = __expf(e[jj]-m); sum += e[jj]; }
#pragma unroll
            for (int o=1;o<8;o<<=1) sum += __shfl_xor_sync(0xffffffffu, sum, o);
            float inv = 1.f/sum;
#pragma unroll
            for (int jj=0;jj<8;jj++) ls[i*ALS + jj*8+g] = e[jj]*inv;
        }
        __syncthreads();
        {
            float a0=0,a1=0,a2=0,a3=0;
            const float* lr = ls + i*ALS;
            for (int j=0;j<64;j++){
                float a = lr[j];
                float4 v4 = *(const float4*)&vs[j*AQS + g*4];
                a0+=a*v4.x; a1+=a*v4.y; a2+=a*v4.z; a3+=a*v4.w;
            }
            float4 r; r.x=a0; r.y=a1; r.z=a2; r.w=a3;
            *(float4*)&ao[tok*Cc + h*HD + g*4] = r;
        }
    }
}

// ---------------- depthwise 3x3 conv, 4-wide x per thread ----------------
__global__ void dwconv4(const float* __restrict__ in, const float* __restrict__ w9,
                        float* __restrict__ out, int C, int doGelu){
    long long idx = (long long)blockIdx.x*blockDim.x + threadIdx.x;
    long long total = (long long)TOK*C/4;
    if (idx >= total) return;
    int c = (int)(idx % C);
    long long t = idx / C;
    int xq = (int)(t & 31);
    int y  = (int)((t >> 5) & 127);
    int b  = (int)(t >> 12);
    int x0 = xq*4;
    const float* base = in + ((size_t)b*LL)*C + c;
    float r[3][6];
#pragma unroll
    for (int ky=0; ky<3; ky++){
        int iy = y + ky - 1;
        bool yok = (unsigned)iy < (unsigned)Hh;
#pragma unroll
        for (int kx=0; kx<6; kx++){
            int ix = x0 + kx - 1;
            bool ok = yok && ((unsigned)ix < (unsigned)Wd);
            r[ky][kx] = ok ? base[((size_t)iy*Wd + ix)*C] : 0.f;
        }
    }
    float wv[9];
#pragma unroll
    for (int k=0;k<9;k++) wv[k] = w9[c*9+k];
    float* ob = out + (((size_t)b*LL) + (size_t)y*Wd + x0)*C + c;
#pragma unroll
    for (int xo=0; xo<4; xo++){
        float acc = 0.f;
#pragma unroll
        for (int ky=0;ky<3;ky++)
#pragma unroll
            for (int kx=0;kx<3;kx++)
                acc += r[ky][xo+kx]*wv[ky*3+kx];
        if (doGelu) acc = gelu_f(acc);
        ob[(size_t)xo*C] = acc;
    }
}

// ---------------- deterministic pooling + channel gate ----------------
__global__ void pool_partial(const float* __restrict__ conv, float* __restrict__ pp){
    int b = blockIdx.y, chunk = blockIdx.x, c = threadIdx.x;
    const float* p = conv + ((size_t)b*LL + (size_t)chunk*128)*Cc + c;
    float s=0.f;
    for (int r=0;r<128;r++) s += p[(size_t)r*Cc];
    pp[(b*128+chunk)*Cc + c] = s;
}

__global__ void pool_final_cm(const float* __restrict__ pp, const float* __restrict__ w1,
                              const float* __restrict__ w2, float* __restrict__ cm){
    int b = blockIdx.x, c = threadIdx.x;
    __shared__ float ps[Cc];
    __shared__ float ts[REDc];
    float s=0.f;
    for (int r=0;r<128;r++) s += pp[(b*128+r)*Cc + c];
    ps[c] = s*(1.f/(float)LL);
    __syncthreads();
    if (c < REDc){
        float t=0.f;
        for (int j=0;j<Cc;j++) t += ps[j]*w1[c*Cc+j];
        ts[c] = gelu_f(t);
    }
    __syncthreads();
    float a=0.f;
#pragma unroll
    for (int r=0;r<REDc;r++) a += ts[r]*w2[c*REDc+r];
    cm[b*Cc+c] = 1.f/(1.f+__expf(-a));
}

// ---------------- residual + LN2 fused ----------------
__global__ void resid_ln2_kernel(const float* __restrict__ x, const float* __restrict__ attn,
    const float* __restrict__ conv, const float* __restrict__ cm,
    const float* __restrict__ w, const float* __restrict__ bb,
    float* __restrict__ xmid, float* __restrict__ n2){
    int warp = (blockIdx.x*blockDim.x + threadIdx.x) >> 5;
    int lane = threadIdx.x & 31;
    if (warp >= TOK) return;
    int b = warp / LL;
    size_t base = (size_t)warp*Cc;
    float v[6]; float s=0.f;
#pragma unroll
    for (int k=0;k<6;k++){
        int c = lane+32*k;
        float xm = x[base+c] + attn[base+c]*cm[b*Cc+c] + conv[base+c];
        xmid[base+c] = xm;
        v[k]=xm; s+=xm;
    }
#pragma unroll
    for (int o=16;o;o>>=1) s += __shfl_xor_sync(0xffffffffu, s, o);
    float mean = s*(1.f/192.f);
    float q = 0.f;
#pragma unroll
    for (int k=0;k<6;k++){ float d=v[k]-mean; q += d*d; }
#pragma unroll
    for (int o=16;o;o>>=1) q += __shfl_xor_sync(0xffffffffu, q, o);
    float inv = rsqrtf(q*(1.f/192.f)+1e-5f);
#pragma unroll
    for (int k=0;k<6;k++){ int c=lane+32*k; n2[base+c] = (v[k]-mean)*inv*w[c]+bb[c]; }
}

// ---------------- launch ----------------
extern "C" void kernel_launch(void* const* d_in, const int* in_sizes, int n_in,
                              void* d_out, int out_size){
    const float* x     = (const float*)d_in[0];
    const float* n1w   = (const float*)d_in[3];
    const float* n1b   = (const float*)d_in[4];
    const float* qkvw  = (const float*)d_in[5];
    const float* projw = (const float*)d_in[6];
    const float* projb = (const float*)d_in[7];
    const float* abias = (const float*)d_in[8];
    const float* convw = (const float*)d_in[9];
    const float* cgw1  = (const float*)d_in[10];
    const float* cgw2  = (const float*)d_in[11];
    const float* n2w   = (const float*)d_in[12];
    const float* n2b   = (const float*)d_in[13];
    const float* fc1w  = (const float*)d_in[14];
    const float* smixw = (const float*)d_in[15];
    const float* fc2w  = (const float*)d_in[16];
    float* out = (float*)d_out;

    float *n1p, *attnp, *convp, *aop, *hp, *h2p, *qkvp, *ppp, *cmp, *wtp;
    cudaGetSymbolAddress((void**)&n1p,   g_n1);
    cudaGetSymbolAddress((void**)&attnp, g_attn);
    cudaGetSymbolAddress((void**)&convp, g_conv);
    cudaGetSymbolAddress((void**)&aop,   g_ao);
    cudaGetSymbolAddress((void**)&hp,    g_h);
    cudaGetSymbolAddress((void**)&h2p,   g_h2);
    cudaGetSymbolAddress((void**)&qkvp,  g_qkv);
    cudaGetSymbolAddress((void**)&ppp,   g_poolp);
    cudaGetSymbolAddress((void**)&cmp,   g_cm);
    cudaGetSymbolAddress((void**)&wtp,   g_wt);

    // 0. weight transposes (tiny)
    transpose_all<<<1152, 256>>>(qkvw, projw, fc1w, fc2w, wtp);
    // 1. n1 = LN1(x)
    ln_kernel<<<TOK/8, 256>>>(x, n1w, n1b, n1p);
    // 2. qkv = n1 @ qkv_w (tf32 mma.sync)
    gemm_mma<<<dim3(QKVN/64, TOK/128), 256>>>(n1p, wtp+WT_QKV, qkvp, nullptr, QKVN, Cc, 0);
    // 3. attention core -> g_ao
    attn_core<<<2048, 512>>>(qkvp, abias, aop);
    // 4. attn_feat = ao @ proj_w + proj_b
    gemm_mma<<<dim3(Cc/64, TOK/128), 256>>>(aop, wtp+WT_PROJ, attnp, projb, Cc, Cc, 2);
    // 5. conv_feat = gelu(dwconv(n1))
    dwconv4<<<(TOK*Cc/4 + 255)/256, 256>>>(n1p, convw, convp, Cc, 1);
    // 6. channel gate
    pool_partial<<<dim3(128, Bsz), Cc>>>(convp, ppp);
    pool_final_cm<<<Bsz, Cc>>>(ppp, cgw1, cgw2, cmp);
    // 7. xmid -> out ; n2 -> g_n1 (reuse)
    resid_ln2_kernel<<<TOK/8, 256>>>(x, attnp, convp, cmp, n2w, n2b, out, n1p);
    // 8. h = gelu(n2 @ fc1_w)
    gemm_mma<<<dim3(HDIMc/64, TOK/128), 256>>>(n1p, wtp+WT_FC1, hp, nullptr, HDIMc, Cc, 1);
    // 9. h2 = dwconv(h)
    dwconv4<<<(TOK*HDIMc/4 + 255)/256, 256>>>(hp, smixw, h2p, HDIMc, 0);
    // 10. out = xmid + h2 @ fc2_w
    gemm_mma<<<dim3(Cc/64, TOK/128), 256>>>(h2p, wtp+WT_FC2, out, out, Cc, HDIMc, 3);
}

// round 8
// speedup vs baseline: 4.5191x; 1.2797x over previous
#include <cuda_runtime.h>
#include <cuda_bf16.h>
#include <cstdint>
#include <math.h>

// ---------------- problem constants ----------------
#define Bsz   8
#define Hh    128
#define Wd    128
#define Cc    192
#define NHh   6
#define HD    32
#define LL    (Hh*Wd)     // 16384
#define TOK   (Bsz*LL)    // 131072
#define HDIMc 384
#define REDc  24
#define QKVN  576

// ---------------- scratch (device globals) ----------------
__device__ float g_n1  [(size_t)TOK*Cc];
__device__ float g_attn[(size_t)TOK*Cc];
__device__ float g_conv[(size_t)TOK*Cc];
__device__ float g_ao  [(size_t)TOK*Cc];
__device__ float g_h   [(size_t)TOK*HDIMc];
__device__ float g_h2  [(size_t)TOK*HDIMc];
__device__ float g_qkv [(size_t)TOK*QKVN];   // used as bf16 (half occupied)
__device__ float g_poolp[Bsz*128*Cc];
__device__ float g_cm  [Bsz*Cc];
__device__ float g_wt  [294912];

#define WT_QKV 0
#define WT_PROJ 110592
#define WT_FC1 147456
#define WT_FC2 221184

__device__ __forceinline__ float gelu_f(float x){
    return 0.5f*x*(1.f + erff(x*0.70710678118654752f));
}
// pack two f32 -> bf16x2 (lo in bits[15:0], hi in bits[31:16])
__device__ __forceinline__ uint32_t packbf(float lo, float hi){
    uint32_t r;
    asm("cvt.rn.bf16x2.f32 %0, %1, %2;" : "=r"(r) : "f"(hi), "f"(lo));
    return r;
}
__device__ __forceinline__ void mma_bf16(float* c, uint32_t a0, uint32_t a1, uint32_t a2, uint32_t a3,
                                         uint32_t b0, uint32_t b1){
    asm volatile("mma.sync.aligned.m16n8k16.row.col.f32.bf16.bf16.f32 "
        "{%0,%1,%2,%3}, {%4,%5,%6,%7}, {%8,%9}, {%0,%1,%2,%3};"
        : "+f"(c[0]), "+f"(c[1]), "+f"(c[2]), "+f"(c[3])
        : "r"(a0), "r"(a1), "r"(a2), "r"(a3), "r"(b0), "r"(b1));
}

// ---------------- weight transpose (tiny) ----------------
__global__ void transpose_all(const float* __restrict__ qkvw, const float* __restrict__ projw,
                              const float* __restrict__ fc1w, const float* __restrict__ fc2w,
                              float* __restrict__ wt){
    int idx = blockIdx.x*256 + threadIdx.x;
    if (idx < 110592){
        int k = idx / QKVN, n = idx % QKVN;
        wt[WT_QKV + n*Cc + k] = qkvw[idx];
    } else if (idx < 147456){
        int l = idx - 110592; int k = l / Cc, n = l % Cc;
        wt[WT_PROJ + n*Cc + k] = projw[l];
    } else if (idx < 221184){
        int l = idx - 147456; int k = l / HDIMc, n = l % HDIMc;
        wt[WT_FC1 + n*Cc + k] = fc1w[l];
    } else if (idx < 294912){
        int l = idx - 221184; int k = l / Cc, n = l % Cc;
        wt[WT_FC2 + n*HDIMc + k] = fc2w[l];
    }
}

// ---------------- bf16 mma GEMM: C[M,N] = A[M,K] @ Bt[N,K]^T ----------------
// BM=128, BN=64, BK=32; 256 thr = 8 warps (4m x 2n), warp tile 32x32, m16n8k16.
// modes: 0 none, 1 gelu, 2 +bias(vec), 3 +residual(mat), 4 bf16-packed output
#define GRS 20   // smem row stride in 32-bit words

__global__ __launch_bounds__(256) void gemm_mma(
    const float* __restrict__ A, const float* __restrict__ Bt,
    float* __restrict__ Cmat, const float* __restrict__ aux,
    int N, int K, int mode)
{
    __shared__ uint32_t As[128*GRS];
    __shared__ uint32_t Bs[64*GRS];
    const int tid = threadIdx.x;
    const int wid = tid >> 5, lane = tid & 31;
    const int wm = wid >> 1, wn = wid & 1;
    const int lg = lane >> 2, lr = lane & 3;
    const int m0 = blockIdx.y << 7, n0 = blockIdx.x << 6;

    float acc[2][4][4] = {};

    const int ldr = tid >> 3;          // 0..31
    const int ldc = (tid & 7) * 4;     // 0,4,...,28 (floats)

    const int nIter = K >> 5;
    for (int it = 0; it < nIter; ++it){
        const int k0 = it << 5;
        #pragma unroll
        for (int p = 0; p < 4; p++){
            int r = ldr + p*32;
            float4 v = *(const float4*)&A[(size_t)(m0 + r)*K + k0 + ldc];
            uint2 w; w.x = packbf(v.x, v.y); w.y = packbf(v.z, v.w);
            *(uint2*)&As[r*GRS + (ldc >> 1)] = w;
        }
        #pragma unroll
        for (int p = 0; p < 2; p++){
            int r = ldr + p*32;
            float4 v = *(const float4*)&Bt[(size_t)(n0 + r)*K + k0 + ldc];
            uint2 w; w.x = packbf(v.x, v.y); w.y = packbf(v.z, v.w);
            *(uint2*)&Bs[r*GRS + (ldc >> 1)] = w;
        }
        __syncthreads();
        #pragma unroll
        for (int kk = 0; kk < 2; kk++){
            uint32_t a[2][4], b[4][2];
            #pragma unroll
            for (int mt = 0; mt < 2; mt++){
                int base = (wm*32 + mt*16 + lg)*GRS + kk*8 + lr;
                a[mt][0] = As[base];
                a[mt][1] = As[base + 8*GRS];
                a[mt][2] = As[base + 4];
                a[mt][3] = As[base + 8*GRS + 4];
            }
            #pragma unroll
            for (int nt = 0; nt < 4; nt++){
                int nb = (wn*32 + nt*8 + lg)*GRS + kk*8 + lr;
                b[nt][0] = Bs[nb];
                b[nt][1] = Bs[nb + 4];
            }
            #pragma unroll
            for (int mt = 0; mt < 2; mt++)
            #pragma unroll
            for (int nt = 0; nt < 4; nt++)
                mma_bf16(acc[mt][nt], a[mt][0], a[mt][1], a[mt][2], a[mt][3],
                         b[nt][0], b[nt][1]);
        }
        __syncthreads();
    }
    // ---- epilogue ----
    #pragma unroll
    for (int mt = 0; mt < 2; mt++){
        #pragma unroll
        for (int rr = 0; rr < 2; rr++){
            int row = m0 + wm*32 + mt*16 + lg + rr*8;
            #pragma unroll
            for (int nt = 0; nt < 4; nt++){
                int col = n0 + wn*32 + nt*8 + lr*2;
                float d0 = acc[mt][nt][rr*2], d1 = acc[mt][nt][rr*2+1];
                size_t o = (size_t)row*N + col;
                if (mode == 1){ d0 = gelu_f(d0); d1 = gelu_f(d1); }
                else if (mode == 2){ d0 += aux[col]; d1 += aux[col+1]; }
                else if (mode == 3){
                    float2 rv = *(const float2*)&aux[o];
                    d0 += rv.x; d1 += rv.y;
                }
                if (mode == 4){
                    ((uint32_t*)Cmat)[o >> 1] = packbf(d0, d1);
                } else {
                    float2 v; v.x = d0; v.y = d1;
                    *(float2*)&Cmat[o] = v;
                }
            }
        }
    }
}

// ---------------- LayerNorm1: one warp per token ----------------
__global__ void ln_kernel(const float* __restrict__ x, const float* __restrict__ w,
                          const float* __restrict__ b, float* __restrict__ out){
    int warp = (blockIdx.x*blockDim.x + threadIdx.x) >> 5;
    int lane = threadIdx.x & 31;
    if (warp >= TOK) return;
    const float* xp = x + (size_t)warp*Cc;
    float v[6]; float s = 0.f;
#pragma unroll
    for (int k=0;k<6;k++){ v[k] = xp[lane+32*k]; s += v[k]; }
#pragma unroll
    for (int o=16;o;o>>=1) s += __shfl_xor_sync(0xffffffffu, s, o);
    float mean = s*(1.f/192.f);
    float q = 0.f;
#pragma unroll
    for (int k=0;k<6;k++){ float d=v[k]-mean; q += d*d; }
#pragma unroll
    for (int o=16;o;o>>=1) q += __shfl_xor_sync(0xffffffffu, q, o);
    float inv = rsqrtf(q*(1.f/192.f)+1e-5f);
    float* op = out + (size_t)warp*Cc;
#pragma unroll
    for (int k=0;k<6;k++){ int c=lane+32*k; op[c] = (v[k]-mean)*inv*w[c]+b[c]; }
}

// ---------------- mma-based window attention ----------------
// One block (256 thr) per 8x8 window. qkv in gmem is PACKED BF16 (288 words/token).
// smem: qs[64][100]w, ks[64][100]w (token-major bf16 pairs over channel),
//       vt[6 heads][32 dims][36]w (dim-major, bf16 pairs over token).
#define AQ_RS 100
#define AV_RS 36
#define ATT_SMEM ((64*AQ_RS*2 + NHh*32*AV_RS)*4)   // 78848 B

__global__ __launch_bounds__(256) void attn_mma(
    const uint32_t* __restrict__ qkvw_, const float* __restrict__ bias,
    float* __restrict__ ao)
{
    extern __shared__ uint32_t ash[];
    uint32_t* qs  = ash;
    uint32_t* ks2 = ash + 64*AQ_RS;
    uint32_t* vt  = ash + 2*64*AQ_RS;

    const int wdx = blockIdx.x;
    const int b = wdx >> 8, wh = (wdx>>4)&15, ww = wdx&15;
    const int tid = threadIdx.x;
    const int wid = tid >> 5, lane = tid & 31;
    const int lg = lane >> 2, lr = lane & 3;

    // ---- fill: 64 tokens x 288 words ----
    uint16_t* vh = (uint16_t*)vt;
    for (int w = tid; w < 64*288; w += 256){
        int t = w / 288, c = w - t*288;
        int lrow = wh*8 + (t>>3), lcol = ww*8 + (t&7);
        size_t tokg = (size_t)b*LL + (size_t)lrow*Wd + lcol;
        uint32_t val = qkvw_[tokg*288 + c];
        if (c < 96){
            qs[t*AQ_RS + c] = val;
        } else if (c < 192){
            ks2[t*AQ_RS + c - 96] = val;
        } else {
            int cc = c - 192;
            int h = cc >> 4;
            int d0 = (cc & 15) << 1;
            uint16_t lo = (uint16_t)(val & 0xFFFFu);
            uint16_t hi = (uint16_t)(val >> 16);
            int wbase = (h*32 + d0)*AV_RS + (t >> 1);
            vh[wbase*2 + (t & 1)] = lo;
            vh[(wbase + AV_RS)*2 + (t & 1)] = hi;
        }
    }
    __syncthreads();

    // ---- 24 tasks = 6 heads x 4 row-slabs(16) over 8 warps ----
    for (int t = wid; t < 24; t += 8){
        const int h = t >> 2, slab = t & 3, row0 = slab*16;
        const int r0 = row0 + lg, r1 = r0 + 8;

        // S = Q @ K^T : 8 n-tiles, K=32 (2 mma k-steps)
        float s[8][4] = {};
        const uint32_t* q0 = qs + r0*AQ_RS + h*16 + lr;
        const uint32_t* q1 = q0 + 8*AQ_RS;
        #pragma unroll
        for (int kk = 0; kk < 2; kk++){
            uint32_t a0 = q0[kk*8], a1 = q1[kk*8], a2 = q0[kk*8+4], a3 = q1[kk*8+4];
            #pragma unroll
            for (int nt = 0; nt < 8; nt++){
                const uint32_t* kr = ks2 + (nt*8+lg)*AQ_RS + h*16 + kk*8 + lr;
                mma_bf16(s[nt], a0, a1, a2, a3, kr[0], kr[4]);
            }
        }

        // scale + bias + softmax (rows r0, r1; cols spread over lr quad)
        const float SC = 0.17677669529663687f;
        const float* bp = bias + (size_t)h*4096;
        float m0 = -1e30f, m1 = -1e30f;
        #pragma unroll
        for (int nt = 0; nt < 8; nt++){
            float2 b0 = *(const float2*)&bp[r0*64 + nt*8 + 2*lr];
            float2 b1 = *(const float2*)&bp[r1*64 + nt*8 + 2*lr];
            s[nt][0] = s[nt][0]*SC + b0.x; s[nt][1] = s[nt][1]*SC + b0.y;
            s[nt][2] = s[nt][2]*SC + b1.x; s[nt][3] = s[nt][3]*SC + b1.y;
            m0 = fmaxf(m0, fmaxf(s[nt][0], s[nt][1]));
            m1 = fmaxf(m1, fmaxf(s[nt][2], s[nt][3]));
        }
        m0 = fmaxf(m0, __shfl_xor_sync(0xffffffffu, m0, 1));
        m0 = fmaxf(m0, __shfl_xor_sync(0xffffffffu, m0, 2));
        m1 = fmaxf(m1, __shfl_xor_sync(0xffffffffu, m1, 1));
        m1 = fmaxf(m1, __shfl_xor_sync(0xffffffffu, m1, 2));
        float s0 = 0.f, s1 = 0.f;
        #pragma unroll
        for (int nt = 0; nt < 8; nt++){
            s[nt][0] = __expf(s[nt][0]-m0); s[nt][1] = __expf(s[nt][1]-m0);
            s[nt][2] = __expf(s[nt][2]-m1); s[nt][3] = __expf(s[nt][3]-m1);
            s0 += s[nt][0] + s[nt][1];
            s1 += s[nt][2] + s[nt][3];
        }
        s0 += __shfl_xor_sync(0xffffffffu, s0, 1);
        s0 += __shfl_xor_sync(0xffffffffu, s0, 2);
        s1 += __shfl_xor_sync(0xffffffffu, s1, 1);
        s1 += __shfl_xor_sync(0xffffffffu, s1, 2);

        // O = P @ V : accumulator fragments feed A directly (layout match)
        float o[4][4] = {};
        #pragma unroll
        for (int sp = 0; sp < 4; sp++){
            uint32_t a0 = packbf(s[2*sp][0],   s[2*sp][1]);
            uint32_t a1 = packbf(s[2*sp][2],   s[2*sp][3]);
            uint32_t a2 = packbf(s[2*sp+1][0], s[2*sp+1][1]);
            uint32_t a3 = packbf(s[2*sp+1][2], s[2*sp+1][3]);
            #pragma unroll
            for (int nd = 0; nd < 4; nd++){
                const uint32_t* vr = vt + (h*32 + nd*8 + lg)*AV_RS + sp*8 + lr;
                mma_bf16(o[nd], a0, a1, a2, a3, vr[0], vr[4]);
            }
        }
        float i0 = 1.f/s0, i1 = 1.f/s1;
        {
            int lrow = wh*8 + (r0>>3), lcol = ww*8 + (r0&7);
            float* op = ao + ((size_t)b*LL + (size_t)lrow*Wd + lcol)*Cc + h*32;
            #pragma unroll
            for (int nd = 0; nd < 4; nd++){
                float2 v; v.x = o[nd][0]*i0; v.y = o[nd][1]*i0;
                *(float2*)&op[nd*8 + 2*lr] = v;
            }
        }
        {
            int lrow = wh*8 + (r1>>3), lcol = ww*8 + (r1&7);
            float* op = ao + ((size_t)b*LL + (size_t)lrow*Wd + lcol)*Cc + h*32;
            #pragma unroll
            for (int nd = 0; nd < 4; nd++){
                float2 v; v.x = o[nd][2]*i1; v.y = o[nd][3]*i1;
                *(float2*)&op[nd*8 + 2*lr] = v;
            }
        }
    }
}

// ---------------- depthwise 3x3 conv, 4-wide x per thread ----------------
__global__ void dwconv4(const float* __restrict__ in, const float* __restrict__ w9,
                        float* __restrict__ out, int C, int doGelu){
    long long idx = (long long)blockIdx.x*blockDim.x + threadIdx.x;
    long long total = (long long)TOK*C/4;
    if (idx >= total) return;
    int c = (int)(idx % C);
    long long t = idx / C;
    int xq = (int)(t & 31);
    int y  = (int)((t >> 5) & 127);
    int b  = (int)(t >> 12);
    int x0 = xq*4;
    const float* base = in + ((size_t)b*LL)*C + c;
    float r[3][6];
#pragma unroll
    for (int ky=0; ky<3; ky++){
        int iy = y + ky - 1;
        bool yok = (unsigned)iy < (unsigned)Hh;
#pragma unroll
        for (int kx=0; kx<6; kx++){
            int ix = x0 + kx - 1;
            bool ok = yok && ((unsigned)ix < (unsigned)Wd);
            r[ky][kx] = ok ? base[((size_t)iy*Wd + ix)*C] : 0.f;
        }
    }
    float wv[9];
#pragma unroll
    for (int k=0;k<9;k++) wv[k] = w9[c*9+k];
    float* ob = out + (((size_t)b*LL) + (size_t)y*Wd + x0)*C + c;
#pragma unroll
    for (int xo=0; xo<4; xo++){
        float acc = 0.f;
#pragma unroll
        for (int ky=0;ky<3;ky++)
#pragma unroll
            for (int kx=0;kx<3;kx++)
                acc += r[ky][xo+kx]*wv[ky*3+kx];
        if (doGelu) acc = gelu_f(acc);
        ob[(size_t)xo*C] = acc;
    }
}

// ---------------- deterministic pooling + channel gate ----------------
__global__ void pool_partial(const float* __restrict__ conv, float* __restrict__ pp){
    int b = blockIdx.y, chunk = blockIdx.x, c = threadIdx.x;
    const float* p = conv + ((size_t)b*LL + (size_t)chunk*128)*Cc + c;
    float s=0.f;
    for (int r=0;r<128;r++) s += p[(size_t)r*Cc];
    pp[(b*128+chunk)*Cc + c] = s;
}

__global__ void pool_final_cm(const float* __restrict__ pp, const float* __restrict__ w1,
                              const float* __restrict__ w2, float* __restrict__ cm){
    int b = blockIdx.x, c = threadIdx.x;
    __shared__ float ps[Cc];
    __shared__ float ts[REDc];
    float s=0.f;
    for (int r=0;r<128;r++) s += pp[(b*128+r)*Cc + c];
    ps[c] = s*(1.f/(float)LL);
    __syncthreads();
    if (c < REDc){
        float t=0.f;
        for (int j=0;j<Cc;j++) t += ps[j]*w1[c*Cc+j];
        ts[c] = gelu_f(t);
    }
    __syncthreads();
    float a=0.f;
#pragma unroll
    for (int r=0;r<REDc;r++) a += ts[r]*w2[c*REDc+r];
    cm[b*Cc+c] = 1.f/(1.f+__expf(-a));
}

// ---------------- residual + LN2 fused ----------------
__global__ void resid_ln2_kernel(const float* __restrict__ x, const float* __restrict__ attn,
    const float* __restrict__ conv, const float* __restrict__ cm,
    const float* __restrict__ w, const float* __restrict__ bb,
    float* __restrict__ xmid, float* __restrict__ n2){
    int warp = (blockIdx.x*blockDim.x + threadIdx.x) >> 5;
    int lane = threadIdx.x & 31;
    if (warp >= TOK) return;
    int b = warp / LL;
    size_t base = (size_t)warp*Cc;
    float v[6]; float s=0.f;
#pragma unroll
    for (int k=0;k<6;k++){
        int c = lane+32*k;
        float xm = x[base+c] + attn[base+c]*cm[b*Cc+c] + conv[base+c];
        xmid[base+c] = xm;
        v[k]=xm; s+=xm;
    }
#pragma unroll
    for (int o=16;o;o>>=1) s += __shfl_xor_sync(0xffffffffu, s, o);
    float mean = s*(1.f/192.f);
    float q = 0.f;
#pragma unroll
    for (int k=0;k<6;k++){ float d=v[k]-mean; q += d*d; }
#pragma unroll
    for (int o=16;o;o>>=1) q += __shfl_xor_sync(0xffffffffu, q, o);
    float inv = rsqrtf(q*(1.f/192.f)+1e-5f);
#pragma unroll
    for (int k=0;k<6;k++){ int c=lane+32*k; n2[base+c] = (v[k]-mean)*inv*w[c]+bb[c]; }
}

// ---------------- launch ----------------
extern "C" void kernel_launch(void* const* d_in, const int* in_sizes, int n_in,
                              void* d_out, int out_size){
    const float* x     = (const float*)d_in[0];
    const float* n1w   = (const float*)d_in[3];
    const float* n1b   = (const float*)d_in[4];
    const float* qkvw  = (const float*)d_in[5];
    const float* projw = (const float*)d_in[6];
    const float* projb = (const float*)d_in[7];
    const float* abias = (const float*)d_in[8];
    const float* convw = (const float*)d_in[9];
    const float* cgw1  = (const float*)d_in[10];
    const float* cgw2  = (const float*)d_in[11];
    const float* n2w   = (const float*)d_in[12];
    const float* n2b   = (const float*)d_in[13];
    const float* fc1w  = (const float*)d_in[14];
    const float* smixw = (const float*)d_in[15];
    const float* fc2w  = (const float*)d_in[16];
    float* out = (float*)d_out;

    float *n1p, *attnp, *convp, *aop, *hp, *h2p, *qkvp, *ppp, *cmp, *wtp;
    cudaGetSymbolAddress((void**)&n1p,   g_n1);
    cudaGetSymbolAddress((void**)&attnp, g_attn);
    cudaGetSymbolAddress((void**)&convp, g_conv);
    cudaGetSymbolAddress((void**)&aop,   g_ao);
    cudaGetSymbolAddress((void**)&hp,    g_h);
    cudaGetSymbolAddress((void**)&h2p,   g_h2);
    cudaGetSymbolAddress((void**)&qkvp,  g_qkv);
    cudaGetSymbolAddress((void**)&ppp,   g_poolp);
    cudaGetSymbolAddress((void**)&cmp,   g_cm);
    cudaGetSymbolAddress((void**)&wtp,   g_wt);

    cudaFuncSetAttribute(attn_mma, cudaFuncAttributeMaxDynamicSharedMemorySize, ATT_SMEM);

    // 0. weight transposes (tiny)
    transpose_all<<<1152, 256>>>(qkvw, projw, fc1w, fc2w, wtp);
    // 1. n1 = LN1(x)
    ln_kernel<<<TOK/8, 256>>>(x, n1w, n1b, n1p);
    // 2. qkv = n1 @ qkv_w  -> packed bf16 output
    gemm_mma<<<dim3(QKVN/64, TOK/128), 256>>>(n1p, wtp+WT_QKV, qkvp, nullptr, QKVN, Cc, 4);
    // 3. mma attention core -> g_ao (fp32)
    attn_mma<<<2048, 256, ATT_SMEM>>>((const uint32_t*)qkvp, abias, aop);
    // 4. attn_feat = ao @ proj_w + proj_b
    gemm_mma<<<dim3(Cc/64, TOK/128), 256>>>(aop, wtp+WT_PROJ, attnp, projb, Cc, Cc, 2);
    // 5. conv_feat = gelu(dwconv(n1))
    dwconv4<<<(TOK*Cc/4 + 255)/256, 256>>>(n1p, convw, convp, Cc, 1);
    // 6. channel gate
    pool_partial<<<dim3(128, Bsz), Cc>>>(convp, ppp);
    pool_final_cm<<<Bsz, Cc>>>(ppp, cgw1, cgw2, cmp);
    // 7. xmid -> out ; n2 -> g_n1 (reuse)
    resid_ln2_kernel<<<TOK/8, 256>>>(x, attnp, convp, cmp, n2w, n2b, out, n1p);
    // 8. h = gelu(n2 @ fc1_w)
    gemm_mma<<<dim3(HDIMc/64, TOK/128), 256>>>(n1p, wtp+WT_FC1, hp, nullptr, HDIMc, Cc, 1);
    // 9. h2 = dwconv(h)
    dwconv4<<<(TOK*HDIMc/4 + 255)/256, 256>>>(hp, smixw, h2p, HDIMc, 0);
    // 10. out = xmid + h2 @ fc2_w
    gemm_mma<<<dim3(Cc/64, TOK/128), 256>>>(h2p, wtp+WT_FC2, out, out, Cc, HDIMc, 3);
}

// round 9
// speedup vs baseline: 5.4246x; 1.2004x over previous
#include <cuda_runtime.h>
#include <cuda_bf16.h>
#include <cstdint>
#include <math.h>

// ---------------- problem constants ----------------
#define Bsz   8
#define Hh    128
#define Wd    128
#define Cc    192
#define NHh   6
#define HD    32
#define LL    (Hh*Wd)     // 16384
#define TOK   (Bsz*LL)    // 131072
#define HDIMc 384
#define REDc  24
#define QKVN  576

// ---------------- scratch (device globals) ----------------
// bf16 buffers stored as packed uint32 (2 halves per word)
__device__ uint32_t g_n1  [(size_t)TOK*96];    // LN1 out, later LN2 out (96 words = 192 ch)
__device__ uint32_t g_ao  [(size_t)TOK*96];    // attention concat-head output (bf16)
__device__ uint32_t g_qkv [(size_t)TOK*288];   // qkv bf16
__device__ uint32_t g_h   [(size_t)TOK*192];   // gelu(fc1) bf16
__device__ uint32_t g_h2  [(size_t)TOK*192];   // dwconv(h) bf16
__device__ uint32_t g_wt  [147456];            // transposed bf16 weights
__device__ float g_attn[(size_t)TOK*Cc];       // proj out (fp32)
__device__ float g_conv[(size_t)TOK*Cc];       // gelu(dwconv(n1)) fp32
__device__ float g_poolp[Bsz*128*Cc];
__device__ float g_cm  [Bsz*Cc];

#define WTB_QKV 0
#define WTB_PROJ 55296
#define WTB_FC1 73728
#define WTB_FC2 110592

__device__ __forceinline__ float gelu_f(float x){
    return 0.5f*x*(1.f + erff(x*0.70710678118654752f));
}
// pack two f32 -> bf16x2 (lo in bits[15:0], hi in bits[31:16])
__device__ __forceinline__ uint32_t packbf(float lo, float hi){
    uint32_t r;
    asm("cvt.rn.bf16x2.f32 %0, %1, %2;" : "=r"(r) : "f"(hi), "f"(lo));
    return r;
}
__device__ __forceinline__ void mma_bf16(float* c, uint32_t a0, uint32_t a1, uint32_t a2, uint32_t a3,
                                         uint32_t b0, uint32_t b1){
    asm volatile("mma.sync.aligned.m16n8k16.row.col.f32.bf16.bf16.f32 "
        "{%0,%1,%2,%3}, {%4,%5,%6,%7}, {%8,%9}, {%0,%1,%2,%3};"
        : "+f"(c[0]), "+f"(c[1]), "+f"(c[2]), "+f"(c[3])
        : "r"(a0), "r"(a1), "r"(a2), "r"(a3), "r"(b0), "r"(b1));
}

// ---------------- weight transpose + bf16 pack (tiny) ----------------
// out word (n, kp) = pack(w[2kp][n], w[2kp+1][n])
__global__ void transpose_all(const float* __restrict__ qkvw, const float* __restrict__ projw,
                              const float* __restrict__ fc1w, const float* __restrict__ fc2w,
                              uint32_t* __restrict__ wt){
    int idx = blockIdx.x*256 + threadIdx.x;
    if (idx < 55296){
        int n = idx / 96, kp = idx % 96;
        wt[WTB_QKV + idx] = packbf(qkvw[(2*kp)*QKVN + n], qkvw[(2*kp+1)*QKVN + n]);
    } else if (idx < 73728){
        int l = idx - 55296; int n = l / 96, kp = l % 96;
        wt[idx] = packbf(projw[(2*kp)*Cc + n], projw[(2*kp+1)*Cc + n]);
    } else if (idx < 110592){
        int l = idx - 73728; int n = l / 96, kp = l % 96;
        wt[idx] = packbf(fc1w[(2*kp)*HDIMc + n], fc1w[(2*kp+1)*HDIMc + n]);
    } else if (idx < 147456){
        int l = idx - 110592; int n = l / 192, kp = l % 192;
        wt[idx] = packbf(fc2w[(2*kp)*Cc + n], fc2w[(2*kp+1)*Cc + n]);
    }
}

// ---------------- bf16 mma GEMM: C[M,N] = A[M,K] @ Bt[N,K]^T ----------------
// A, Bt are packed bf16 (K/2 words per row). BM=128, BN=64, BK=32.
// 256 thr = 8 warps (4m x 2n), warp tile 32x32, m16n8k16.
// modes: 2 +bias(vec,f32 out), 3 +residual(mat,f32 out), 4 bf16 out, 5 gelu+bf16 out
#define GRS 20

__global__ __launch_bounds__(256) void gemm_mma(
    const uint32_t* __restrict__ A, const uint32_t* __restrict__ Bt,
    void* __restrict__ Cmat, const float* __restrict__ aux,
    int N, int K, int mode)
{
    __shared__ uint32_t As[128*GRS];
    __shared__ uint32_t Bs[64*GRS];
    const int tid = threadIdx.x;
    const int wid = tid >> 5, lane = tid & 31;
    const int wm = wid >> 1, wn = wid & 1;
    const int lg = lane >> 2, lr = lane & 3;
    const int m0 = blockIdx.y << 7, n0 = blockIdx.x << 6;
    const int Kw = K >> 1;

    float acc[2][4][4] = {};

    const int ra = tid >> 1, wa = (tid & 1) * 8;
    const int rb = tid >> 2, wb = (tid & 3) * 4;

    const int nIter = K >> 5;
    for (int it = 0; it < nIter; ++it){
        const int k0w = it << 4;
        {
            const uint32_t* ap = A + (size_t)(m0 + ra)*Kw + k0w + wa;
            *(uint4*)&As[ra*GRS + wa]     = *(const uint4*)ap;
            *(uint4*)&As[ra*GRS + wa + 4] = *(const uint4*)(ap + 4);
            *(uint4*)&Bs[rb*GRS + wb] = *(const uint4*)&Bt[(size_t)(n0 + rb)*Kw + k0w + wb];
        }
        __syncthreads();
        #pragma unroll
        for (int kk = 0; kk < 2; kk++){
            uint32_t a[2][4], b[4][2];
            #pragma unroll
            for (int mt = 0; mt < 2; mt++){
                int base = (wm*32 + mt*16 + lg)*GRS + kk*8 + lr;
                a[mt][0] = As[base];
                a[mt][1] = As[base + 8*GRS];
                a[mt][2] = As[base + 4];
                a[mt][3] = As[base + 8*GRS + 4];
            }
            #pragma unroll
            for (int nt = 0; nt < 4; nt++){
                int nb = (wn*32 + nt*8 + lg)*GRS + kk*8 + lr;
                b[nt][0] = Bs[nb];
                b[nt][1] = Bs[nb + 4];
            }
            #pragma unroll
            for (int mt = 0; mt < 2; mt++)
            #pragma unroll
            for (int nt = 0; nt < 4; nt++)
                mma_bf16(acc[mt][nt], a[mt][0], a[mt][1], a[mt][2], a[mt][3],
                         b[nt][0], b[nt][1]);
        }
        __syncthreads();
    }
    // ---- epilogue ----
    #pragma unroll
    for (int mt = 0; mt < 2; mt++){
        #pragma unroll
        for (int rr = 0; rr < 2; rr++){
            int row = m0 + wm*32 + mt*16 + lg + rr*8;
            #pragma unroll
            for (int nt = 0; nt < 4; nt++){
                int col = n0 + wn*32 + nt*8 + lr*2;
                float d0 = acc[mt][nt][rr*2], d1 = acc[mt][nt][rr*2+1];
                size_t o = (size_t)row*N + col;
                if (mode == 2){
                    d0 += aux[col]; d1 += aux[col+1];
                    float2 v; v.x = d0; v.y = d1;
                    *(float2*)((float*)Cmat + o) = v;
                } else if (mode == 3){
                    float2 rv = *(const float2*)&aux[o];
                    float2 v; v.x = d0 + rv.x; v.y = d1 + rv.y;
                    *(float2*)((float*)Cmat + o) = v;
                } else if (mode == 4){
                    ((uint32_t*)Cmat)[o >> 1] = packbf(d0, d1);
                } else { // 5: gelu + bf16
                    ((uint32_t*)Cmat)[o >> 1] = packbf(gelu_f(d0), gelu_f(d1));
                }
            }
        }
    }
}

// ---------------- LayerNorm: one warp per token, bf16 packed out ----------------
__global__ void ln_kernel(const float* __restrict__ x, const float* __restrict__ w,
                          const float* __restrict__ b, uint32_t* __restrict__ out){
    int warp = (blockIdx.x*blockDim.x + threadIdx.x) >> 5;
    int lane = threadIdx.x & 31;
    if (warp >= TOK) return;
    const float* xp = x + (size_t)warp*Cc;
    float v[3][2]; float s = 0.f;
#pragma unroll
    for (int k=0;k<3;k++){
        float2 t = *(const float2*)&xp[2*(lane+32*k)];
        v[k][0]=t.x; v[k][1]=t.y; s += t.x + t.y;
    }
#pragma unroll
    for (int o=16;o;o>>=1) s += __shfl_xor_sync(0xffffffffu, s, o);
    float mean = s*(1.f/192.f);
    float q = 0.f;
#pragma unroll
    for (int k=0;k<3;k++){ float d0=v[k][0]-mean, d1=v[k][1]-mean; q += d0*d0 + d1*d1; }
#pragma unroll
    for (int o=16;o;o>>=1) q += __shfl_xor_sync(0xffffffffu, q, o);
    float inv = rsqrtf(q*(1.f/192.f)+1e-5f);
    uint32_t* op = out + (size_t)warp*96;
#pragma unroll
    for (int k=0;k<3;k++){
        int c2 = lane+32*k;
        float r0 = (v[k][0]-mean)*inv*w[2*c2]+b[2*c2];
        float r1 = (v[k][1]-mean)*inv*w[2*c2+1]+b[2*c2+1];
        op[c2] = packbf(r0, r1);
    }
}

// ---------------- mma window attention: block = (window, head-pair) ----------------
#define AQ_S 20
#define AV_S 36

__global__ __launch_bounds__(256) void attn_mma(
    const uint32_t* __restrict__ qkv, const float* __restrict__ bias,
    uint32_t* __restrict__ ao)
{
    __shared__ uint32_t qs[2*64*AQ_S];
    __shared__ uint32_t ks[2*64*AQ_S];
    __shared__ uint32_t vt[2*32*AV_S];

    const int win = blockIdx.x, hp = blockIdx.y;
    const int b = win >> 8, wh = (win>>4)&15, ww = win&15;
    const int h0 = hp*2;
    const int tid = threadIdx.x;
    const int wid = tid >> 5, lane = tid & 31;
    const int lg = lane >> 2, lr = lane & 3;

    // ---- fill: 4 lanes per token, contiguous 32-word segments per head-pair ----
    {
        int t = tid >> 2, l4 = tid & 3;
        int lrow = wh*8 + (t>>3), lcol = ww*8 + (t&7);
        const uint32_t* src = qkv + ((size_t)b*LL + (size_t)lrow*Wd + lcol)*288;
        uint16_t* vh = (uint16_t*)vt;
        #pragma unroll
        for (int u = 0; u < 2; u++){
            int wofs = l4*8 + u*4;
            uint32_t vq[4], vk[4], vv[4];
            *(uint4*)vq = *(const uint4*)&src[h0*16 + wofs];
            *(uint4*)vk = *(const uint4*)&src[96 + h0*16 + wofs];
            *(uint4*)vv = *(const uint4*)&src[192 + h0*16 + wofs];
            #pragma unroll
            for (int i = 0; i < 4; i++){
                int w = wofs + i;          // 0..31 within head-pair
                int hh = w >> 4, wl = w & 15;
                qs[(hh*64 + t)*AQ_S + wl] = vq[i];
                ks[(hh*64 + t)*AQ_S + wl] = vk[i];
                // v scatter: dims d0=2*wl, d0+1 of head hh, token t
                int base0 = ((hh*32 + 2*wl)*AV_S + (t>>1))*2 + (t&1);
                vh[base0]            = (uint16_t)(vv[i] & 0xFFFFu);
                vh[base0 + 2*AV_S]   = (uint16_t)(vv[i] >> 16);
            }
        }
    }
    __syncthreads();

    // ---- one task per warp: h = wid>>2 (0/1), slab = wid&3 ----
    const int h = wid >> 2, slab = wid & 3;
    const int r0 = slab*16 + lg, r1 = r0 + 8;
    const uint32_t* qsh = qs + h*64*AQ_S;
    const uint32_t* ksh = ks + h*64*AQ_S;

    // S = Q @ K^T
    float s[8][4] = {};
    {
        const uint32_t* q0 = qsh + r0*AQ_S + lr;
        const uint32_t* q1 = q0 + 8*AQ_S;
        #pragma unroll
        for (int kk = 0; kk < 2; kk++){
            uint32_t a0 = q0[kk*8], a1 = q1[kk*8], a2 = q0[kk*8+4], a3 = q1[kk*8+4];
            #pragma unroll
            for (int nt = 0; nt < 8; nt++){
                const uint32_t* kr = ksh + (nt*8+lg)*AQ_S + kk*8 + lr;
                mma_bf16(s[nt], a0, a1, a2, a3, kr[0], kr[4]);
            }
        }
    }

    // scale + bias + softmax
    const float SC = 0.17677669529663687f;
    const float* bp = bias + (size_t)(h0+h)*4096;
    float m0 = -1e30f, m1 = -1e30f;
    #pragma unroll
    for (int nt = 0; nt < 8; nt++){
        float2 b0 = *(const float2*)&bp[r0*64 + nt*8 + 2*lr];
        float2 b1 = *(const float2*)&bp[r1*64 + nt*8 + 2*lr];
        s[nt][0] = s[nt][0]*SC + b0.x; s[nt][1] = s[nt][1]*SC + b0.y;
        s[nt][2] = s[nt][2]*SC + b1.x; s[nt][3] = s[nt][3]*SC + b1.y;
        m0 = fmaxf(m0, fmaxf(s[nt][0], s[nt][1]));
        m1 = fmaxf(m1, fmaxf(s[nt][2], s[nt][3]));
    }
    m0 = fmaxf(m0, __shfl_xor_sync(0xffffffffu, m0, 1));
    m0 = fmaxf(m0, __shfl_xor_sync(0xffffffffu, m0, 2));
    m1 = fmaxf(m1, __shfl_xor_sync(0xffffffffu, m1, 1));
    m1 = fmaxf(m1, __shfl_xor_sync(0xffffffffu, m1, 2));
    float s0 = 0.f, s1 = 0.f;
    #pragma unroll
    for (int nt = 0; nt < 8; nt++){
        s[nt][0] = __expf(s[nt][0]-m0); s[nt][1] = __expf(s[nt][1]-m0);
        s[nt][2] = __expf(s[nt][2]-m1); s[nt][3] = __expf(s[nt][3]-m1);
        s0 += s[nt][0] + s[nt][1];
        s1 += s[nt][2] + s[nt][3];
    }
    s0 += __shfl_xor_sync(0xffffffffu, s0, 1);
    s0 += __shfl_xor_sync(0xffffffffu, s0, 2);
    s1 += __shfl_xor_sync(0xffffffffu, s1, 1);
    s1 += __shfl_xor_sync(0xffffffffu, s1, 2);

    // O = P @ V
    float o[4][4] = {};
    #pragma unroll
    for (int sp = 0; sp < 4; sp++){
        uint32_t a0 = packbf(s[2*sp][0],   s[2*sp][1]);
        uint32_t a1 = packbf(s[2*sp][2],   s[2*sp][3]);
        uint32_t a2 = packbf(s[2*sp+1][0], s[2*sp+1][1]);
        uint32_t a3 = packbf(s[2*sp+1][2], s[2*sp+1][3]);
        #pragma unroll
        for (int nd = 0; nd < 4; nd++){
            const uint32_t* vr = vt + (h*32 + nd*8 + lg)*AV_S + sp*8 + lr;
            mma_bf16(o[nd], a0, a1, a2, a3, vr[0], vr[4]);
        }
    }
    float i0 = 1.f/s0, i1 = 1.f/s1;
    {
        int lrow = wh*8 + (r0>>3), lcol = ww*8 + (r0&7);
        uint32_t* op = ao + ((size_t)b*LL + (size_t)lrow*Wd + lcol)*96 + (h0+h)*16;
        #pragma unroll
        for (int nd = 0; nd < 4; nd++)
            op[nd*4 + lr] = packbf(o[nd][0]*i0, o[nd][1]*i0);
    }
    {
        int lrow = wh*8 + (r1>>3), lcol = ww*8 + (r1&7);
        uint32_t* op = ao + ((size_t)b*LL + (size_t)lrow*Wd + lcol)*96 + (h0+h)*16;
        #pragma unroll
        for (int nd = 0; nd < 4; nd++)
            op[nd*4 + lr] = packbf(o[nd][2]*i1, o[nd][3]*i1);
    }
}

// ---------------- depthwise 3x3 conv, bf16 in, 4-wide x per thread ----------------
// outBf: 0 -> fp32 out (with gelu), 1 -> bf16 out (no gelu)
__global__ void dwconv4(const __nv_bfloat16* __restrict__ in, const float* __restrict__ w9,
                        void* __restrict__ out, int C, int outBf){
    long long idx = (long long)blockIdx.x*blockDim.x + threadIdx.x;
    long long total = (long long)TOK*C/4;
    if (idx >= total) return;
    int c = (int)(idx % C);
    long long t = idx / C;
    int xq = (int)(t & 31);
    int y  = (int)((t >> 5) & 127);
    int b  = (int)(t >> 12);
    int x0 = xq*4;
    const __nv_bfloat16* base = in + ((size_t)b*LL)*C + c;
    float r[3][6];
#pragma unroll
    for (int ky=0; ky<3; ky++){
        int iy = y + ky - 1;
        bool yok = (unsigned)iy < (unsigned)Hh;
#pragma unroll
        for (int kx=0; kx<6; kx++){
            int ix = x0 + kx - 1;
            bool ok = yok && ((unsigned)ix < (unsigned)Wd);
            r[ky][kx] = ok ? __bfloat162float(base[((size_t)iy*Wd + ix)*C]) : 0.f;
        }
    }
    float wv[9];
#pragma unroll
    for (int k=0;k<9;k++) wv[k] = w9[c*9+k];
    size_t ob = (((size_t)b*LL) + (size_t)y*Wd + x0)*C + c;
#pragma unroll
    for (int xo=0; xo<4; xo++){
        float acc = 0.f;
#pragma unroll
        for (int ky=0;ky<3;ky++)
#pragma unroll
            for (int kx=0;kx<3;kx++)
                acc += r[ky][xo+kx]*wv[ky*3+kx];
        if (outBf){
            ((__nv_bfloat16*)out)[ob + (size_t)xo*C] = __float2bfloat16(acc);
        } else {
            ((float*)out)[ob + (size_t)xo*C] = gelu_f(acc);
        }
    }
}

// ---------------- deterministic pooling + channel gate ----------------
__global__ void pool_partial(const float* __restrict__ conv, float* __restrict__ pp){
    int b = blockIdx.y, chunk = blockIdx.x, c = threadIdx.x;
    const float* p = conv + ((size_t)b*LL + (size_t)chunk*128)*Cc + c;
    float s=0.f;
    for (int r=0;r<128;r++) s += p[(size_t)r*Cc];
    pp[(b*128+chunk)*Cc + c] = s;
}

__global__ void pool_final_cm(const float* __restrict__ pp, const float* __restrict__ w1,
                              const float* __restrict__ w2, float* __restrict__ cm){
    int b = blockIdx.x, c = threadIdx.x;
    __shared__ float ps[Cc];
    __shared__ float ts[REDc];
    float s=0.f;
    for (int r=0;r<128;r++) s += pp[(b*128+r)*Cc + c];
    ps[c] = s*(1.f/(float)LL);
    __syncthreads();
    if (c < REDc){
        float t=0.f;
        for (int j=0;j<Cc;j++) t += ps[j]*w1[c*Cc+j];
        ts[c] = gelu_f(t);
    }
    __syncthreads();
    float a=0.f;
#pragma unroll
    for (int r=0;r<REDc;r++) a += ts[r]*w2[c*REDc+r];
    cm[b*Cc+c] = 1.f/(1.f+__expf(-a));
}

// ---------------- residual + LN2 fused: xmid fp32, n2 bf16 ----------------
__global__ void resid_ln2_kernel(const float* __restrict__ x, const float* __restrict__ attn,
    const float* __restrict__ conv, const float* __restrict__ cm,
    const float* __restrict__ w, const float* __restrict__ bb,
    float* __restrict__ xmid, uint32_t* __restrict__ n2){
    int warp = (blockIdx.x*blockDim.x + threadIdx.x) >> 5;
    int lane = threadIdx.x & 31;
    if (warp >= TOK) return;
    int b = warp / LL;
    size_t base = (size_t)warp*Cc;
    float v[3][2]; float s=0.f;
#pragma unroll
    for (int k=0;k<3;k++){
        int c = 2*(lane+32*k);
        float2 xv = *(const float2*)&x[base+c];
        float2 av = *(const float2*)&attn[base+c];
        float2 cv = *(const float2*)&conv[base+c];
        float2 gv = *(const float2*)&cm[b*Cc+c];
        float m0 = xv.x + av.x*gv.x + cv.x;
        float m1 = xv.y + av.y*gv.y + cv.y;
        float2 o; o.x=m0; o.y=m1;
        *(float2*)&xmid[base+c] = o;
        v[k][0]=m0; v[k][1]=m1; s+=m0+m1;
    }
#pragma unroll
    for (int o=16;o;o>>=1) s += __shfl_xor_sync(0xffffffffu, s, o);
    float mean = s*(1.f/192.f);
    float q = 0.f;
#pragma unroll
    for (int k=0;k<3;k++){ float d0=v[k][0]-mean, d1=v[k][1]-mean; q += d0*d0 + d1*d1; }
#pragma unroll
    for (int o=16;o;o>>=1) q += __shfl_xor_sync(0xffffffffu, q, o);
    float inv = rsqrtf(q*(1.f/192.f)+1e-5f);
    uint32_t* op = n2 + (size_t)warp*96;
#pragma unroll
    for (int k=0;k<3;k++){
        int c2 = lane+32*k;
        float r0 = (v[k][0]-mean)*inv*w[2*c2]+bb[2*c2];
        float r1 = (v[k][1]-mean)*inv*w[2*c2+1]+bb[2*c2+1];
        op[c2] = packbf(r0, r1);
    }
}

// ---------------- launch ----------------
extern "C" void kernel_launch(void* const* d_in, const int* in_sizes, int n_in,
                              void* d_out, int out_size){
    const float* x     = (const float*)d_in[0];
    const float* n1w   = (const float*)d_in[3];
    const float* n1b   = (const float*)d_in[4];
    const float* qkvw  = (const float*)d_in[5];
    const float* projw = (const float*)d_in[6];
    const float* projb = (const float*)d_in[7];
    const float* abias = (const float*)d_in[8];
    const float* convw = (const float*)d_in[9];
    const float* cgw1  = (const float*)d_in[10];
    const float* cgw2  = (const float*)d_in[11];
    const float* n2w   = (const float*)d_in[12];
    const float* n2b   = (const float*)d_in[13];
    const float* fc1w  = (const float*)d_in[14];
    const float* smixw = (const float*)d_in[15];
    const float* fc2w  = (const float*)d_in[16];
    float* out = (float*)d_out;

    uint32_t *n1p, *aop, *qkvp, *hp, *h2p, *wtp;
    float *attnp, *convp, *ppp, *cmp;
    cudaGetSymbolAddress((void**)&n1p,   g_n1);
    cudaGetSymbolAddress((void**)&aop,   g_ao);
    cudaGetSymbolAddress((void**)&qkvp,  g_qkv);
    cudaGetSymbolAddress((void**)&hp,    g_h);
    cudaGetSymbolAddress((void**)&h2p,   g_h2);
    cudaGetSymbolAddress((void**)&wtp,   g_wt);
    cudaGetSymbolAddress((void**)&attnp, g_attn);
    cudaGetSymbolAddress((void**)&convp, g_conv);
    cudaGetSymbolAddress((void**)&ppp,   g_poolp);
    cudaGetSymbolAddress((void**)&cmp,   g_cm);

    // 0. weight transposes -> bf16 (tiny)
    transpose_all<<<576, 256>>>(qkvw, projw, fc1w, fc2w, wtp);
    // 1. n1 = LN1(x) -> bf16
    ln_kernel<<<TOK/8, 256>>>(x, n1w, n1b, n1p);
    // 2. qkv = n1 @ qkv_w -> bf16
    gemm_mma<<<dim3(QKVN/64, TOK/128), 256>>>(n1p, wtp+WTB_QKV, qkvp, nullptr, QKVN, Cc, 4);
    // 3. attention -> ao (bf16)
    attn_mma<<<dim3(2048, 3), 256>>>(qkvp, abias, aop);
    // 4. attn_feat = ao @ proj_w + proj_b -> fp32
    gemm_mma<<<dim3(Cc/64, TOK/128), 256>>>(aop, wtp+WTB_PROJ, attnp, projb, Cc, Cc, 2);
    // 5. conv_feat = gelu(dwconv(n1)) -> fp32
    dwconv4<<<(TOK*Cc/4 + 255)/256, 256>>>((const __nv_bfloat16*)n1p, convw, convp, Cc, 0);
    // 6. channel gate
    pool_partial<<<dim3(128, Bsz), Cc>>>(convp, ppp);
    pool_final_cm<<<Bsz, Cc>>>(ppp, cgw1, cgw2, cmp);
    // 7. xmid -> out (fp32) ; n2 -> g_n1 (bf16, reuse)
    resid_ln2_kernel<<<TOK/8, 256>>>(x, attnp, convp, cmp, n2w, n2b, out, n1p);
    // 8. h = gelu(n2 @ fc1_w) -> bf16
    gemm_mma<<<dim3(HDIMc/64, TOK/128), 256>>>(n1p, wtp+WTB_FC1, hp, nullptr, HDIMc, Cc, 5);
    // 9. h2 = dwconv(h) -> bf16
    dwconv4<<<(TOK*HDIMc/4 + 255)/256, 256>>>((const __nv_bfloat16*)hp, smixw, h2p, HDIMc, 1);
    // 10. out = xmid + h2 @ fc2_w (fp32 residual in-place)
    gemm_mma<<<dim3(Cc/64, TOK/128), 256>>>(h2p, wtp+WTB_FC2, out, out, Cc, HDIMc, 3);
}

// round 11
// speedup vs baseline: 6.5002x; 1.1983x over previous
#include <cuda_runtime.h>
#include <cuda_bf16.h>
#include <cstdint>
#include <math.h>

// ---------------- problem constants ----------------
#define Bsz   8
#define Hh    128
#define Wd    128
#define Cc    192
#define NHh   6
#define HD    32
#define LL    (Hh*Wd)     // 16384
#define TOK   (Bsz*LL)    // 131072
#define HDIMc 384
#define REDc  24
#define QKVN  576

// ---------------- scratch (device globals) ----------------
__device__ uint32_t g_n1  [(size_t)TOK*96];    // LN1 out, later LN2 out (bf16 packed)
__device__ uint32_t g_ao  [(size_t)TOK*96];    // attention concat-head output (bf16)
__device__ uint32_t g_qkv [(size_t)TOK*288];   // qkv bf16
__device__ uint32_t g_h   [(size_t)TOK*192];   // gelu(fc1) bf16
__device__ uint32_t g_h2  [(size_t)TOK*192];   // dwconv(h) bf16
__device__ uint32_t g_wt  [147456];            // transposed bf16 weights
__device__ uint32_t g_attn[(size_t)TOK*96];    // proj out (bf16 packed)
__device__ uint32_t g_conv[(size_t)TOK*96];    // gelu(dwconv(n1)) (bf16 packed)
__device__ float g_poolp[Bsz*128*Cc];
__device__ float g_cm  [Bsz*Cc];

#define WTB_QKV 0
#define WTB_PROJ 55296
#define WTB_FC1 73728
#define WTB_FC2 110592

__device__ __forceinline__ float gelu_f(float x){
    return 0.5f*x*(1.f + erff(x*0.70710678118654752f));
}
__device__ __forceinline__ uint32_t packbf(float lo, float hi){
    uint32_t r;
    asm("cvt.rn.bf16x2.f32 %0, %1, %2;" : "=r"(r) : "f"(hi), "f"(lo));
    return r;
}
__device__ __forceinline__ float2 unpackbf(uint32_t w){
    __nv_bfloat162 h = *reinterpret_cast<__nv_bfloat162*>(&w);
    float2 r; r.x = __bfloat162float(h.x); r.y = __bfloat162float(h.y);
    return r;
}
__device__ __forceinline__ void mma_bf16(float* c, uint32_t a0, uint32_t a1, uint32_t a2, uint32_t a3,
                                         uint32_t b0, uint32_t b1){
    asm volatile("mma.sync.aligned.m16n8k16.row.col.f32.bf16.bf16.f32 "
        "{%0,%1,%2,%3}, {%4,%5,%6,%7}, {%8,%9}, {%0,%1,%2,%3};"
        : "+f"(c[0]), "+f"(c[1]), "+f"(c[2]), "+f"(c[3])
        : "r"(a0), "r"(a1), "r"(a2), "r"(a3), "r"(b0), "r"(b1));
}
__device__ __forceinline__ void cpasync16(uint32_t saddr, const void* g){
    asm volatile("cp.async.ca.shared.global [%0], [%1], 16;" :: "r"(saddr), "l"(g));
}
__device__ __forceinline__ void ldm_x4(uint32_t* r, uint32_t saddr){
    asm volatile("ldmatrix.sync.aligned.m8n8.x4.shared.b16 {%0,%1,%2,%3}, [%4];"
        : "=r"(r[0]), "=r"(r[1]), "=r"(r[2]), "=r"(r[3]) : "r"(saddr));
}

// ---------------- weight transpose + bf16 pack (tiny) ----------------
__global__ void transpose_all(const float* __restrict__ qkvw, const float* __restrict__ projw,
                              const float* __restrict__ fc1w, const float* __restrict__ fc2w,
                              uint32_t* __restrict__ wt){
    int idx = blockIdx.x*256 + threadIdx.x;
    if (idx < 55296){
        int n = idx / 96, kp = idx % 96;
        wt[WTB_QKV + idx] = packbf(qkvw[(2*kp)*QKVN + n], qkvw[(2*kp+1)*QKVN + n]);
    } else if (idx < 73728){
        int l = idx - 55296; int n = l / 96, kp = l % 96;
        wt[idx] = packbf(projw[(2*kp)*Cc + n], projw[(2*kp+1)*Cc + n]);
    } else if (idx < 110592){
        int l = idx - 73728; int n = l / 96, kp = l % 96;
        wt[idx] = packbf(fc1w[(2*kp)*HDIMc + n], fc1w[(2*kp+1)*HDIMc + n]);
    } else if (idx < 147456){
        int l = idx - 110592; int n = l / 192, kp = l % 192;
        wt[idx] = packbf(fc2w[(2*kp)*Cc + n], fc2w[(2*kp+1)*Cc + n]);
    }
}

// ---------------- bf16 mma GEMM, cp.async 2-stage + ldmatrix ----------------
// C[M,N] = A[M,K] @ Bt[N,K]^T. A, Bt packed bf16 (K/2 words/row).
// BM=128, BN=64, BK=32; 8 warps (4m x 2n), warp tile 32x32.
// modes: 3 +residual(mat,f32 out), 4 bf16 out, 5 gelu+bf16 out, 6 +bias -> bf16 out
#define GRS 20
#define ASTAGE (128*GRS*4)
#define BSTAGE (64*GRS*4)

__global__ __launch_bounds__(256) void gemm_mma(
    const uint32_t* __restrict__ A, const uint32_t* __restrict__ Bt,
    void* __restrict__ Cmat, const float* __restrict__ aux,
    int N, int K, int mode)
{
    __shared__ uint32_t As[2][128*GRS];
    __shared__ uint32_t Bs[2][64*GRS];
    const int tid = threadIdx.x;
    const int wid = tid >> 5, lane = tid & 31;
    const int wm = wid >> 1, wn = wid & 1;
    const int lg = lane >> 2, lr = lane & 3;
    const int m0 = blockIdx.y << 7, n0 = blockIdx.x << 6;
    const int Kw = K >> 1;

    const uint32_t aBase = (uint32_t)__cvta_generic_to_shared(&As[0][0]);
    const uint32_t bBase = (uint32_t)__cvta_generic_to_shared(&Bs[0][0]);

    float acc[2][4][4] = {};

    // loader: A = 512 x 16B chunks (2/thread), B = 256 chunks (1/thread)
    const int ca0 = tid, ca1 = tid + 256;
    const int ra0 = ca0 >> 2, oa0 = (ca0 & 3) * 4;
    const int ra1 = ca1 >> 2, oa1 = (ca1 & 3) * 4;
    const int rb  = tid >> 2, ob  = (tid & 3) * 4;

    // ldmatrix per-warp byte offsets (within a stage)
    const int l16 = lane & 15, lh = lane >> 4;
    uint32_t aoffm[2];
    #pragma unroll
    for (int mt = 0; mt < 2; mt++)
        aoffm[mt] = ((wm*32 + mt*16 + l16)*GRS + lh*4)*4;
    const int b8 = lane & 7, sel = lane >> 3;
    uint32_t boffp[2];
    #pragma unroll
    for (int p = 0; p < 2; p++)
        boffp[p] = ((wn*32 + p*16 + (sel>>1)*8 + b8)*GRS + (sel&1)*4)*4;

    const int nIter = K >> 5;
    // prologue load
    {
        const int k0w = 0;
        cpasync16(aBase + (ra0*GRS+oa0)*4, A + (size_t)(m0+ra0)*Kw + k0w + oa0);
        cpasync16(aBase + (ra1*GRS+oa1)*4, A + (size_t)(m0+ra1)*Kw + k0w + oa1);
        cpasync16(bBase + (rb*GRS+ob)*4,  Bt + (size_t)(n0+rb)*Kw + k0w + ob);
        asm volatile("cp.async.commit_group;");
    }
    int st = 0;
    for (int it = 0; it < nIter; ++it){
        if (it + 1 < nIter){
            const int k0w = (it+1) << 4;
            const int ns = st ^ 1;
            cpasync16(aBase + ns*ASTAGE + (ra0*GRS+oa0)*4, A + (size_t)(m0+ra0)*Kw + k0w + oa0);
            cpasync16(aBase + ns*ASTAGE + (ra1*GRS+oa1)*4, A + (size_t)(m0+ra1)*Kw + k0w + oa1);
            cpasync16(bBase + ns*BSTAGE + (rb*GRS+ob)*4,  Bt + (size_t)(n0+rb)*Kw + k0w + ob);
            asm volatile("cp.async.commit_group;");
            asm volatile("cp.async.wait_group 1;");
        } else {
            asm volatile("cp.async.wait_group 0;");
        }
        __syncthreads();
        const uint32_t aS = aBase + st*ASTAGE, bS = bBase + st*BSTAGE;
        #pragma unroll
        for (int kk = 0; kk < 2; kk++){
            uint32_t a[2][4], b[2][4];
            ldm_x4(a[0], aS + aoffm[0] + kk*32);
            ldm_x4(a[1], aS + aoffm[1] + kk*32);
            ldm_x4(b[0], bS + boffp[0] + kk*32);
            ldm_x4(b[1], bS + boffp[1] + kk*32);
            #pragma unroll
            for (int mt = 0; mt < 2; mt++)
            #pragma unroll
            for (int nt = 0; nt < 4; nt++)
                mma_bf16(acc[mt][nt], a[mt][0], a[mt][1], a[mt][2], a[mt][3],
                         b[nt>>1][(nt&1)*2], b[nt>>1][(nt&1)*2+1]);
        }
        __syncthreads();
        st ^= 1;
    }
    // ---- epilogue ----
    #pragma unroll
    for (int mt = 0; mt < 2; mt++){
        #pragma unroll
        for (int rr = 0; rr < 2; rr++){
            int row = m0 + wm*32 + mt*16 + lg + rr*8;
            #pragma unroll
            for (int nt = 0; nt < 4; nt++){
                int col = n0 + wn*32 + nt*8 + lr*2;
                float d0 = acc[mt][nt][rr*2], d1 = acc[mt][nt][rr*2+1];
                size_t o = (size_t)row*N + col;
                if (mode == 3){
                    float2 rv = *(const float2*)&aux[o];
                    float2 v; v.x = d0 + rv.x; v.y = d1 + rv.y;
                    *(float2*)((float*)Cmat + o) = v;
                } else if (mode == 4){
                    ((uint32_t*)Cmat)[o >> 1] = packbf(d0, d1);
                } else if (mode == 5){
                    ((uint32_t*)Cmat)[o >> 1] = packbf(gelu_f(d0), gelu_f(d1));
                } else { // 6: +bias -> bf16
                    ((uint32_t*)Cmat)[o >> 1] = packbf(d0 + aux[col], d1 + aux[col+1]);
                }
            }
        }
    }
}

// ---------------- LayerNorm: one warp per token, bf16 packed out ----------------
__global__ void ln_kernel(const float* __restrict__ x, const float* __restrict__ w,
                          const float* __restrict__ b, uint32_t* __restrict__ out){
    int warp = (blockIdx.x*blockDim.x + threadIdx.x) >> 5;
    int lane = threadIdx.x & 31;
    if (warp >= TOK) return;
    const float* xp = x + (size_t)warp*Cc;
    float v[3][2]; float s = 0.f;
#pragma unroll
    for (int k=0;k<3;k++){
        float2 t = *(const float2*)&xp[2*(lane+32*k)];
        v[k][0]=t.x; v[k][1]=t.y; s += t.x + t.y;
    }
#pragma unroll
    for (int o=16;o;o>>=1) s += __shfl_xor_sync(0xffffffffu, s, o);
    float mean = s*(1.f/192.f);
    float q = 0.f;
#pragma unroll
    for (int k=0;k<3;k++){ float d0=v[k][0]-mean, d1=v[k][1]-mean; q += d0*d0 + d1*d1; }
#pragma unroll
    for (int o=16;o;o>>=1) q += __shfl_xor_sync(0xffffffffu, q, o);
    float inv = rsqrtf(q*(1.f/192.f)+1e-5f);
    uint32_t* op = out + (size_t)warp*96;
#pragma unroll
    for (int k=0;k<3;k++){
        int c2 = lane+32*k;
        float r0 = (v[k][0]-mean)*inv*w[2*c2]+b[2*c2];
        float r1 = (v[k][1]-mean)*inv*w[2*c2+1]+b[2*c2+1];
        op[c2] = packbf(r0, r1);
    }
}

// ---------------- mma window attention: block = (window, head-pair) ----------------
#define AQ_S 20
#define AV_S 36

__global__ __launch_bounds__(256) void attn_mma(
    const uint32_t* __restrict__ qkv, const float* __restrict__ bias,
    uint32_t* __restrict__ ao)
{
    __shared__ uint32_t qs[2*64*AQ_S];
    __shared__ uint32_t ks[2*64*AQ_S];
    __shared__ uint32_t vt[2*32*AV_S];

    const int win = blockIdx.x, hp = blockIdx.y;
    const int b = win >> 8, wh = (win>>4)&15, ww = win&15;
    const int h0 = hp*2;
    const int tid = threadIdx.x;
    const int wid = tid >> 5, lane = tid & 31;
    const int lg = lane >> 2, lr = lane & 3;

    {
        int t = tid >> 2, l4 = tid & 3;
        int lrow = wh*8 + (t>>3), lcol = ww*8 + (t&7);
        const uint32_t* src = qkv + ((size_t)b*LL + (size_t)lrow*Wd + lcol)*288;
        uint16_t* vh = (uint16_t*)vt;
        #pragma unroll
        for (int u = 0; u < 2; u++){
            int wofs = l4*8 + u*4;
            uint32_t vq[4], vk[4], vv[4];
            *(uint4*)vq = *(const uint4*)&src[h0*16 + wofs];
            *(uint4*)vk = *(const uint4*)&src[96 + h0*16 + wofs];
            *(uint4*)vv = *(const uint4*)&src[192 + h0*16 + wofs];
            #pragma unroll
            for (int i = 0; i < 4; i++){
                int w = wofs + i;
                int hh = w >> 4, wl = w & 15;
                qs[(hh*64 + t)*AQ_S + wl] = vq[i];
                ks[(hh*64 + t)*AQ_S + wl] = vk[i];
                int base0 = ((hh*32 + 2*wl)*AV_S + (t>>1))*2 + (t&1);
                vh[base0]          = (uint16_t)(vv[i] & 0xFFFFu);
                vh[base0 + 2*AV_S] = (uint16_t)(vv[i] >> 16);
            }
        }
    }
    __syncthreads();

    const int h = wid >> 2, slab = wid & 3;
    const int r0 = slab*16 + lg, r1 = r0 + 8;
    const uint32_t* qsh = qs + h*64*AQ_S;
    const uint32_t* ksh = ks + h*64*AQ_S;

    float s[8][4] = {};
    {
        const uint32_t* q0 = qsh + r0*AQ_S + lr;
        const uint32_t* q1 = q0 + 8*AQ_S;
        #pragma unroll
        for (int kk = 0; kk < 2; kk++){
            uint32_t a0 = q0[kk*8], a1 = q1[kk*8], a2 = q0[kk*8+4], a3 = q1[kk*8+4];
            #pragma unroll
            for (int nt = 0; nt < 8; nt++){
                const uint32_t* kr = ksh + (nt*8+lg)*AQ_S + kk*8 + lr;
                mma_bf16(s[nt], a0, a1, a2, a3, kr[0], kr[4]);
            }
        }
    }

    const float SC = 0.17677669529663687f;
    const float* bp = bias + (size_t)(h0+h)*4096;
    float m0 = -1e30f, m1 = -1e30f;
    #pragma unroll
    for (int nt = 0; nt < 8; nt++){
        float2 b0 = *(const float2*)&bp[r0*64 + nt*8 + 2*lr];
        float2 b1 = *(const float2*)&bp[r1*64 + nt*8 + 2*lr];
        s[nt][0] = s[nt][0]*SC + b0.x; s[nt][1] = s[nt][1]*SC + b0.y;
        s[nt][2] = s[nt][2]*SC + b1.x; s[nt][3] = s[nt][3]*SC + b1.y;
        m0 = fmaxf(m0, fmaxf(s[nt][0], s[nt][1]));
        m1 = fmaxf(m1, fmaxf(s[nt][2], s[nt][3]));
    }
    m0 = fmaxf(m0, __shfl_xor_sync(0xffffffffu, m0, 1));
    m0 = fmaxf(m0, __shfl_xor_sync(0xffffffffu, m0, 2));
    m1 = fmaxf(m1, __shfl_xor_sync(0xffffffffu, m1, 1));
    m1 = fmaxf(m1, __shfl_xor_sync(0xffffffffu, m1, 2));
    float s0 = 0.f, s1 = 0.f;
    #pragma unroll
    for (int nt = 0; nt < 8; nt++){
        s[nt][0] = __expf(s[nt][0]-m0); s[nt][1] = __expf(s[nt][1]-m0);
        s[nt][2] = __expf(s[nt][2]-m1); s[nt][3] = __expf(s[nt][3]-m1);
        s0 += s[nt][0] + s[nt][1];
        s1 += s[nt][2] + s[nt][3];
    }
    s0 += __shfl_xor_sync(0xffffffffu, s0, 1);
    s0 += __shfl_xor_sync(0xffffffffu, s0, 2);
    s1 += __shfl_xor_sync(0xffffffffu, s1, 1);
    s1 += __shfl_xor_sync(0xffffffffu, s1, 2);

    float o[4][4] = {};
    #pragma unroll
    for (int sp = 0; sp < 4; sp++){
        uint32_t a0 = packbf(s[2*sp][0],   s[2*sp][1]);
        uint32_t a1 = packbf(s[2*sp][2],   s[2*sp][3]);
        uint32_t a2 = packbf(s[2*sp+1][0], s[2*sp+1][1]);
        uint32_t a3 = packbf(s[2*sp+1][2], s[2*sp+1][3]);
        #pragma unroll
        for (int nd = 0; nd < 4; nd++){
            const uint32_t* vr = vt + (h*32 + nd*8 + lg)*AV_S + sp*8 + lr;
            mma_bf16(o[nd], a0, a1, a2, a3, vr[0], vr[4]);
        }
    }
    float i0 = 1.f/s0, i1 = 1.f/s1;
    {
        int lrow = wh*8 + (r0>>3), lcol = ww*8 + (r0&7);
        uint32_t* op = ao + ((size_t)b*LL + (size_t)lrow*Wd + lcol)*96 + (h0+h)*16;
        #pragma unroll
        for (int nd = 0; nd < 4; nd++)
            op[nd*4 + lr] = packbf(o[nd][0]*i0, o[nd][1]*i0);
    }
    {
        int lrow = wh*8 + (r1>>3), lcol = ww*8 + (r1&7);
        uint32_t* op = ao + ((size_t)b*LL + (size_t)lrow*Wd + lcol)*96 + (h0+h)*16;
        #pragma unroll
        for (int nd = 0; nd < 4; nd++)
            op[nd*4 + lr] = packbf(o[nd][2]*i1, o[nd][3]*i1);
    }
}

// ---------------- depthwise 3x3 conv, bf16 in, bf16 out ----------------
// doGelu: 1 -> gelu before store ; 0 -> plain
__global__ void dwconv4(const __nv_bfloat16* __restrict__ in, const float* __restrict__ w9,
                        __nv_bfloat16* __restrict__ out, int C, int doGelu){
    long long idx = (long long)blockIdx.x*blockDim.x + threadIdx.x;
    long long total = (long long)TOK*C/4;
    if (idx >= total) return;
    int c = (int)(idx % C);
    long long t = idx / C;
    int xq = (int)(t & 31);
    int y  = (int)((t >> 5) & 127);
    int b  = (int)(t >> 12);
    int x0 = xq*4;
    const __nv_bfloat16* base = in + ((size_t)b*LL)*C + c;
    float r[3][6];
#pragma unroll
    for (int ky=0; ky<3; ky++){
        int iy = y + ky - 1;
        bool yok = (unsigned)iy < (unsigned)Hh;
#pragma unroll
        for (int kx=0; kx<6; kx++){
            int ix = x0 + kx - 1;
            bool ok = yok && ((unsigned)ix < (unsigned)Wd);
            r[ky][kx] = ok ? __bfloat162float(base[((size_t)iy*Wd + ix)*C]) : 0.f;
        }
    }
    float wv[9];
#pragma unroll
    for (int k=0;k<9;k++) wv[k] = w9[c*9+k];
    size_t ob = (((size_t)b*LL) + (size_t)y*Wd + x0)*C + c;
#pragma unroll
    for (int xo=0; xo<4; xo++){
        float acc = 0.f;
#pragma unroll
        for (int ky=0;ky<3;ky++)
#pragma unroll
            for (int kx=0;kx<3;kx++)
                acc += r[ky][xo+kx]*wv[ky*3+kx];
        if (doGelu) acc = gelu_f(acc);
        out[ob + (size_t)xo*C] = __float2bfloat16(acc);
    }
}

// ---------------- deterministic pooling + channel gate (bf16 conv in) ----------------
__global__ void pool_partial(const __nv_bfloat16* __restrict__ conv, float* __restrict__ pp){
    int b = blockIdx.y, chunk = blockIdx.x, c = threadIdx.x;
    const __nv_bfloat16* p = conv + ((size_t)b*LL + (size_t)chunk*128)*Cc + c;
    float s=0.f;
    for (int r=0;r<128;r++) s += __bfloat162float(p[(size_t)r*Cc]);
    pp[(b*128+chunk)*Cc + c] = s;
}

__global__ void pool_final_cm(const float* __restrict__ pp, const float* __restrict__ w1,
                              const float* __restrict__ w2, float* __restrict__ cm){
    int b = blockIdx.x, c = threadIdx.x;
    __shared__ float ps[Cc];
    __shared__ float ts[REDc];
    float s=0.f;
    for (int r=0;r<128;r++) s += pp[(b*128+r)*Cc + c];
    ps[c] = s*(1.f/(float)LL);
    __syncthreads();
    if (c < REDc){
        float t=0.f;
        for (int j=0;j<Cc;j++) t += ps[j]*w1[c*Cc+j];
        ts[c] = gelu_f(t);
    }
    __syncthreads();
    float a=0.f;
#pragma unroll
    for (int r=0;r<REDc;r++) a += ts[r]*w2[c*REDc+r];
    cm[b*Cc+c] = 1.f/(1.f+__expf(-a));
}

// ---------------- residual + LN2 fused: attn/conv bf16 in, xmid fp32, n2 bf16 ----------------
__global__ void resid_ln2_kernel(const float* __restrict__ x, const uint32_t* __restrict__ attn,
    const uint32_t* __restrict__ conv, const float* __restrict__ cm,
    const float* __restrict__ w, const float* __restrict__ bb,
    float* __restrict__ xmid, uint32_t* __restrict__ n2){
    int warp = (blockIdx.x*blockDim.x + threadIdx.x) >> 5;
    int lane = threadIdx.x & 31;
    if (warp >= TOK) return;
    int b = warp / LL;
    size_t base = (size_t)warp*Cc;
    float v[3][2]; float s=0.f;
#pragma unroll
    for (int k=0;k<3;k++){
        int c2 = lane+32*k;
        int c = 2*c2;
        float2 xv = *(const float2*)&x[base+c];
        float2 av = unpackbf(attn[(size_t)warp*96 + c2]);
        float2 cv = unpackbf(conv[(size_t)warp*96 + c2]);
        float2 gv = *(const float2*)&cm[b*Cc+c];
        float m0 = xv.x + av.x*gv.x + cv.x;
        float m1 = xv.y + av.y*gv.y + cv.y;
        float2 o; o.x=m0; o.y=m1;
        *(float2*)&xmid[base+c] = o;
        v[k][0]=m0; v[k][1]=m1; s+=m0+m1;
    }
#pragma unroll
    for (int o=16;o;o>>=1) s += __shfl_xor_sync(0xffffffffu, s, o);
    float mean = s*(1.f/192.f);
    float q = 0.f;
#pragma unroll
    for (int k=0;k<3;k++){ float d0=v[k][0]-mean, d1=v[k][1]-mean; q += d0*d0 + d1*d1; }
#pragma unroll
    for (int o=16;o;o>>=1) q += __shfl_xor_sync(0xffffffffu, q, o);
    float inv = rsqrtf(q*(1.f/192.f)+1e-5f);
    uint32_t* op = n2 + (size_t)warp*96;
#pragma unroll
    for (int k=0;k<3;k++){
        int c2 = lane+32*k;
        float r0 = (v[k][0]-mean)*inv*w[2*c2]+bb[2*c2];
        float r1 = (v[k][1]-mean)*inv*w[2*c2+1]+bb[2*c2+1];
        op[c2] = packbf(r0, r1);
    }
}

// ---------------- launch ----------------
extern "C" void kernel_launch(void* const* d_in, const int* in_sizes, int n_in,
                              void* d_out, int out_size){
    const float* x     = (const float*)d_in[0];
    const float* n1w   = (const float*)d_in[3];
    const float* n1b   = (const float*)d_in[4];
    const float* qkvw  = (const float*)d_in[5];
    const float* projw = (const float*)d_in[6];
    const float* projb = (const float*)d_in[7];
    const float* abias = (const float*)d_in[8];
    const float* convw = (const float*)d_in[9];
    const float* cgw1  = (const float*)d_in[10];
    const float* cgw2  = (const float*)d_in[11];
    const float* n2w   = (const float*)d_in[12];
    const float* n2b   = (const float*)d_in[13];
    const float* fc1w  = (const float*)d_in[14];
    const float* smixw = (const float*)d_in[15];
    const float* fc2w  = (const float*)d_in[16];
    float* out = (float*)d_out;

    uint32_t *n1p, *aop, *qkvp, *hp, *h2p, *wtp, *attnp, *convp;
    float *ppp, *cmp;
    cudaGetSymbolAddress((void**)&n1p,   g_n1);
    cudaGetSymbolAddress((void**)&aop,   g_ao);
    cudaGetSymbolAddress((void**)&qkvp,  g_qkv);
    cudaGetSymbolAddress((void**)&hp,    g_h);
    cudaGetSymbolAddress((void**)&h2p,   g_h2);
    cudaGetSymbolAddress((void**)&wtp,   g_wt);
    cudaGetSymbolAddress((void**)&attnp, g_attn);
    cudaGetSymbolAddress((void**)&convp, g_conv);
    cudaGetSymbolAddress((void**)&ppp,   g_poolp);
    cudaGetSymbolAddress((void**)&cmp,   g_cm);

    // 0. weight transposes -> bf16 (tiny)
    transpose_all<<<576, 256>>>(qkvw, projw, fc1w, fc2w, wtp);
    // 1. n1 = LN1(x) -> bf16
    ln_kernel<<<TOK/8, 256>>>(x, n1w, n1b, n1p);
    // 2. qkv = n1 @ qkv_w -> bf16
    gemm_mma<<<dim3(QKVN/64, TOK/128), 256>>>(n1p, wtp+WTB_QKV, qkvp, nullptr, QKVN, Cc, 4);
    // 3. attention -> ao (bf16)
    attn_mma<<<dim3(2048, 3), 256>>>(qkvp, abias, aop);
    // 4. attn_feat = ao @ proj_w + proj_b -> bf16
    gemm_mma<<<dim3(Cc/64, TOK/128), 256>>>(aop, wtp+WTB_PROJ, attnp, projb, Cc, Cc, 6);
    // 5. conv_feat = gelu(dwconv(n1)) -> bf16  (GELU ON)
    dwconv4<<<(TOK*Cc/4 + 255)/256, 256>>>((const __nv_bfloat16*)n1p, convw,
                                           (__nv_bfloat16*)convp, Cc, 1);
    // 6. channel gate
    pool_partial<<<dim3(128, Bsz), Cc>>>((const __nv_bfloat16*)convp, ppp);
    pool_final_cm<<<Bsz, Cc>>>(ppp, cgw1, cgw2, cmp);
    // 7. xmid -> out (fp32) ; n2 -> g_n1 (bf16, reuse)
    resid_ln2_kernel<<<TOK/8, 256>>>(x, attnp, convp, cmp, n2w, n2b, out, n1p);
    // 8. h = gelu(n2 @ fc1_w) -> bf16
    gemm_mma<<<dim3(HDIMc/64, TOK/128), 256>>>(n1p, wtp+WTB_FC1, hp, nullptr, HDIMc, Cc, 5);
    // 9. h2 = dwconv(h) -> bf16  (NO GELU — this was the R10 bug)
    dwconv4<<<(TOK*HDIMc/4 + 255)/256, 256>>>((const __nv_bfloat16*)hp, smixw,
                                              (__nv_bfloat16*)h2p, HDIMc, 0);
    // 10. out = xmid + h2 @ fc2_w (fp32 residual in-place)
    gemm_mma<<<dim3(Cc/64, TOK/128), 256>>>(h2p, wtp+WTB_FC2, out, out, Cc, HDIMc, 3);
}

// round 12
// speedup vs baseline: 6.7120x; 1.0326x over previous
#include <cuda_runtime.h>
#include <cuda_bf16.h>
#include <cstdint>
#include <math.h>

// ---------------- problem constants ----------------
#define Bsz   8
#define Hh    128
#define Wd    128
#define Cc    192
#define NHh   6
#define HD    32
#define LL    (Hh*Wd)     // 16384
#define TOK   (Bsz*LL)    // 131072
#define HDIMc 384
#define REDc  24
#define QKVN  576

// ---------------- scratch (device globals) ----------------
__device__ uint32_t g_n1  [(size_t)TOK*96];    // LN1 out, later LN2 out (bf16 packed)
__device__ uint32_t g_ao  [(size_t)TOK*96];    // attention concat-head output (bf16)
__device__ uint32_t g_qkv [(size_t)TOK*288];   // qkv bf16
__device__ uint32_t g_h   [(size_t)TOK*192];   // gelu(fc1) bf16
__device__ uint32_t g_h2  [(size_t)TOK*192];   // dwconv(h) bf16
__device__ uint32_t g_wt  [147456];            // transposed bf16 weights
__device__ uint32_t g_attn[(size_t)TOK*96];    // proj out (bf16 packed)
__device__ uint32_t g_conv[(size_t)TOK*96];    // gelu(dwconv(n1)) (bf16 packed)
__device__ float g_poolp[Bsz*128*Cc];
__device__ float g_cm  [Bsz*Cc];

#define WTB_QKV 0
#define WTB_PROJ 55296
#define WTB_FC1 73728
#define WTB_FC2 110592

__device__ __forceinline__ float gelu_f(float x){
    return 0.5f*x*(1.f + erff(x*0.70710678118654752f));
}
__device__ __forceinline__ uint32_t packbf(float lo, float hi){
    uint32_t r;
    asm("cvt.rn.bf16x2.f32 %0, %1, %2;" : "=r"(r) : "f"(hi), "f"(lo));
    return r;
}
__device__ __forceinline__ float2 unpackbf(uint32_t w){
    __nv_bfloat162 h = *reinterpret_cast<__nv_bfloat162*>(&w);
    float2 r; r.x = __bfloat162float(h.x); r.y = __bfloat162float(h.y);
    return r;
}
__device__ __forceinline__ void mma_bf16(float* c, uint32_t a0, uint32_t a1, uint32_t a2, uint32_t a3,
                                         uint32_t b0, uint32_t b1){
    asm volatile("mma.sync.aligned.m16n8k16.row.col.f32.bf16.bf16.f32 "
        "{%0,%1,%2,%3}, {%4,%5,%6,%7}, {%8,%9}, {%0,%1,%2,%3};"
        : "+f"(c[0]), "+f"(c[1]), "+f"(c[2]), "+f"(c[3])
        : "r"(a0), "r"(a1), "r"(a2), "r"(a3), "r"(b0), "r"(b1));
}
__device__ __forceinline__ void cpasync16(uint32_t saddr, const void* g){
    asm volatile("cp.async.ca.shared.global [%0], [%1], 16;" :: "r"(saddr), "l"(g));
}
__device__ __forceinline__ void ldm_x4(uint32_t* r, uint32_t saddr){
    asm volatile("ldmatrix.sync.aligned.m8n8.x4.shared.b16 {%0,%1,%2,%3}, [%4];"
        : "=r"(r[0]), "=r"(r[1]), "=r"(r[2]), "=r"(r[3]) : "r"(saddr));
}

// ---------------- weight transpose + bf16 pack (tiny) ----------------
__global__ void transpose_all(const float* __restrict__ qkvw, const float* __restrict__ projw,
                              const float* __restrict__ fc1w, const float* __restrict__ fc2w,
                              uint32_t* __restrict__ wt){
    int idx = blockIdx.x*256 + threadIdx.x;
    if (idx < 55296){
        int n = idx / 96, kp = idx % 96;
        wt[WTB_QKV + idx] = packbf(qkvw[(2*kp)*QKVN + n], qkvw[(2*kp+1)*QKVN + n]);
    } else if (idx < 73728){
        int l = idx - 55296; int n = l / 96, kp = l % 96;
        wt[idx] = packbf(projw[(2*kp)*Cc + n], projw[(2*kp+1)*Cc + n]);
    } else if (idx < 110592){
        int l = idx - 73728; int n = l / 96, kp = l % 96;
        wt[idx] = packbf(fc1w[(2*kp)*HDIMc + n], fc1w[(2*kp+1)*HDIMc + n]);
    } else if (idx < 147456){
        int l = idx - 110592; int n = l / 192, kp = l % 192;
        wt[idx] = packbf(fc2w[(2*kp)*Cc + n], fc2w[(2*kp+1)*Cc + n]);
    }
}

// ---------------- bf16 mma GEMM, cp.async 2-stage + ldmatrix ----------------
// C[M,N] = A[M,K] @ Bt[N,K]^T. A, Bt packed bf16 (K/2 words/row).
// BM=256, BN=64, BK=32; 8 warps (4m x 2n), warp tile 64x32.
// dynamic smem: As[2][256*GRS] then Bs[2][64*GRS].
// modes: 3 +residual(mat,f32 out), 4 bf16 out, 5 gelu+bf16 out, 6 +bias -> bf16 out
#define GRS 20
#define ASTAGE (256*GRS*4)
#define BSTAGE (64*GRS*4)
#define GEMM_SMEM (2*(ASTAGE + BSTAGE))   // 51200 B

__global__ __launch_bounds__(256) void gemm_mma(
    const uint32_t* __restrict__ A, const uint32_t* __restrict__ Bt,
    void* __restrict__ Cmat, const float* __restrict__ aux,
    int N, int K, int mode)
{
    extern __shared__ uint32_t gsm[];
    const int tid = threadIdx.x;
    const int wid = tid >> 5, lane = tid & 31;
    const int wm = wid >> 1, wn = wid & 1;
    const int lg = lane >> 2, lr = lane & 3;
    const int m0 = blockIdx.y << 8, n0 = blockIdx.x << 6;
    const int Kw = K >> 1;

    const uint32_t sBase = (uint32_t)__cvta_generic_to_shared(gsm);
    const uint32_t aBase = sBase;
    const uint32_t bBase = sBase + 2*ASTAGE;

    float acc[4][4][4] = {};

    // loaders: A = 1024 x 16B chunks (4/thread), B = 256 chunks (1/thread)
    const int raw = tid >> 2, oaw = (tid & 3) * 4;

    // ldmatrix per-warp byte offsets (within a stage)
    const int l16 = lane & 15, lh = lane >> 4;
    uint32_t aoffm[4];
    #pragma unroll
    for (int mt = 0; mt < 4; mt++)
        aoffm[mt] = ((wm*64 + mt*16 + l16)*GRS + lh*4)*4;
    const int b8 = lane & 7, sel = lane >> 3;
    uint32_t boffp[2];
    #pragma unroll
    for (int p = 0; p < 2; p++)
        boffp[p] = ((wn*32 + p*16 + (sel>>1)*8 + b8)*GRS + (sel&1)*4)*4;

    const int nIter = K >> 5;
    // prologue load (stage 0)
    {
        #pragma unroll
        for (int i = 0; i < 4; i++)
            cpasync16(aBase + ((raw + 64*i)*GRS + oaw)*4,
                      A + (size_t)(m0 + raw + 64*i)*Kw + oaw);
        cpasync16(bBase + (raw*GRS + oaw)*4, Bt + (size_t)(n0 + raw)*Kw + oaw);
        asm volatile("cp.async.commit_group;");
    }
    int st = 0;
    for (int it = 0; it < nIter; ++it){
        if (it + 1 < nIter){
            const int k0w = (it+1) << 4;
            const int ns = st ^ 1;
            #pragma unroll
            for (int i = 0; i < 4; i++)
                cpasync16(aBase + ns*ASTAGE + ((raw + 64*i)*GRS + oaw)*4,
                          A + (size_t)(m0 + raw + 64*i)*Kw + k0w + oaw);
            cpasync16(bBase + ns*BSTAGE + (raw*GRS + oaw)*4,
                      Bt + (size_t)(n0 + raw)*Kw + k0w + oaw);
            asm volatile("cp.async.commit_group;");
            asm volatile("cp.async.wait_group 1;");
        } else {
            asm volatile("cp.async.wait_group 0;");
        }
        __syncthreads();
        const uint32_t aS = aBase + st*ASTAGE, bS = bBase + st*BSTAGE;
        #pragma unroll
        for (int kk = 0; kk < 2; kk++){
            uint32_t a[4][4], b[2][4];
            #pragma unroll
            for (int mt = 0; mt < 4; mt++)
                ldm_x4(a[mt], aS + aoffm[mt] + kk*32);
            ldm_x4(b[0], bS + boffp[0] + kk*32);
            ldm_x4(b[1], bS + boffp[1] + kk*32);
            #pragma unroll
            for (int mt = 0; mt < 4; mt++)
            #pragma unroll
            for (int nt = 0; nt < 4; nt++)
                mma_bf16(acc[mt][nt], a[mt][0], a[mt][1], a[mt][2], a[mt][3],
                         b[nt>>1][(nt&1)*2], b[nt>>1][(nt&1)*2+1]);
        }
        __syncthreads();
        st ^= 1;
    }
    // ---- epilogue ----
    #pragma unroll
    for (int mt = 0; mt < 4; mt++){
        #pragma unroll
        for (int rr = 0; rr < 2; rr++){
            int row = m0 + wm*64 + mt*16 + lg + rr*8;
            #pragma unroll
            for (int nt = 0; nt < 4; nt++){
                int col = n0 + wn*32 + nt*8 + lr*2;
                float d0 = acc[mt][nt][rr*2], d1 = acc[mt][nt][rr*2+1];
                size_t o = (size_t)row*N + col;
                if (mode == 3){
                    float2 rv = *(const float2*)&aux[o];
                    float2 v; v.x = d0 + rv.x; v.y = d1 + rv.y;
                    *(float2*)((float*)Cmat + o) = v;
                } else if (mode == 4){
                    ((uint32_t*)Cmat)[o >> 1] = packbf(d0, d1);
                } else if (mode == 5){
                    ((uint32_t*)Cmat)[o >> 1] = packbf(gelu_f(d0), gelu_f(d1));
                } else { // 6: +bias -> bf16
                    ((uint32_t*)Cmat)[o >> 1] = packbf(d0 + aux[col], d1 + aux[col+1]);
                }
            }
        }
    }
}

// ---------------- LayerNorm: one warp per token, bf16 packed out ----------------
__global__ void ln_kernel(const float* __restrict__ x, const float* __restrict__ w,
                          const float* __restrict__ b, uint32_t* __restrict__ out){
    int warp = (blockIdx.x*blockDim.x + threadIdx.x) >> 5;
    int lane = threadIdx.x & 31;
    if (warp >= TOK) return;
    const float* xp = x + (size_t)warp*Cc;
    float v[3][2]; float s = 0.f;
#pragma unroll
    for (int k=0;k<3;k++){
        float2 t = *(const float2*)&xp[2*(lane+32*k)];
        v[k][0]=t.x; v[k][1]=t.y; s += t.x + t.y;
    }
#pragma unroll
    for (int o=16;o;o>>=1) s += __shfl_xor_sync(0xffffffffu, s, o);
    float mean = s*(1.f/192.f);
    float q = 0.f;
#pragma unroll
    for (int k=0;k<3;k++){ float d0=v[k][0]-mean, d1=v[k][1]-mean; q += d0*d0 + d1*d1; }
#pragma unroll
    for (int o=16;o;o>>=1) q += __shfl_xor_sync(0xffffffffu, q, o);
    float inv = rsqrtf(q*(1.f/192.f)+1e-5f);
    uint32_t* op = out + (size_t)warp*96;
#pragma unroll
    for (int k=0;k<3;k++){
        int c2 = lane+32*k;
        float r0 = (v[k][0]-mean)*inv*w[2*c2]+b[2*c2];
        float r1 = (v[k][1]-mean)*inv*w[2*c2+1]+b[2*c2+1];
        op[c2] = packbf(r0, r1);
    }
}

// ---------------- mma window attention: block = (window, head-pair) ----------------
#define AQ_S 20
#define AV_S 36

__global__ __launch_bounds__(256) void attn_mma(
    const uint32_t* __restrict__ qkv, const float* __restrict__ bias,
    uint32_t* __restrict__ ao)
{
    __shared__ uint32_t qs[2*64*AQ_S];
    __shared__ uint32_t ks[2*64*AQ_S];
    __shared__ uint32_t vt[2*32*AV_S];

    const int win = blockIdx.x, hp = blockIdx.y;
    const int b = win >> 8, wh = (win>>4)&15, ww = win&15;
    const int h0 = hp*2;
    const int tid = threadIdx.x;
    const int wid = tid >> 5, lane = tid & 31;
    const int lg = lane >> 2, lr = lane & 3;

    {
        int t = tid >> 2, l4 = tid & 3;
        int lrow = wh*8 + (t>>3), lcol = ww*8 + (t&7);
        const uint32_t* src = qkv + ((size_t)b*LL + (size_t)lrow*Wd + lcol)*288;
        uint16_t* vh = (uint16_t*)vt;
        #pragma unroll
        for (int u = 0; u < 2; u++){
            int wofs = l4*8 + u*4;
            uint32_t vq[4], vk[4], vv[4];
            *(uint4*)vq = *(const uint4*)&src[h0*16 + wofs];
            *(uint4*)vk = *(const uint4*)&src[96 + h0*16 + wofs];
            *(uint4*)vv = *(const uint4*)&src[192 + h0*16 + wofs];
            #pragma unroll
            for (int i = 0; i < 4; i++){
                int w = wofs + i;
                int hh = w >> 4, wl = w & 15;
                qs[(hh*64 + t)*AQ_S + wl] = vq[i];
                ks[(hh*64 + t)*AQ_S + wl] = vk[i];
                int base0 = ((hh*32 + 2*wl)*AV_S + (t>>1))*2 + (t&1);
                vh[base0]          = (uint16_t)(vv[i] & 0xFFFFu);
                vh[base0 + 2*AV_S] = (uint16_t)(vv[i] >> 16);
            }
        }
    }
    __syncthreads();

    const int h = wid >> 2, slab = wid & 3;
    const int r0 = slab*16 + lg, r1 = r0 + 8;
    const uint32_t* qsh = qs + h*64*AQ_S;
    const uint32_t* ksh = ks + h*64*AQ_S;

    float s[8][4] = {};
    {
        const uint32_t* q0 = qsh + r0*AQ_S + lr;
        const uint32_t* q1 = q0 + 8*AQ_S;
        #pragma unroll
        for (int kk = 0; kk < 2; kk++){
            uint32_t a0 = q0[kk*8], a1 = q1[kk*8], a2 = q0[kk*8+4], a3 = q1[kk*8+4];
            #pragma unroll
            for (int nt = 0; nt < 8; nt++){
                const uint32_t* kr = ksh + (nt*8+lg)*AQ_S + kk*8 + lr;
                mma_bf16(s[nt], a0, a1, a2, a3, kr[0], kr[4]);
            }
        }
    }

    const float SC = 0.17677669529663687f;
    const float* bp = bias + (size_t)(h0+h)*4096;
    float m0 = -1e30f, m1 = -1e30f;
    #pragma unroll
    for (int nt = 0; nt < 8; nt++){
        float2 b0 = *(const float2*)&bp[r0*64 + nt*8 + 2*lr];
        float2 b1 = *(const float2*)&bp[r1*64 + nt*8 + 2*lr];
        s[nt][0] = s[nt][0]*SC + b0.x; s[nt][1] = s[nt][1]*SC + b0.y;
        s[nt][2] = s[nt][2]*SC + b1.x; s[nt][3] = s[nt][3]*SC + b1.y;
        m0 = fmaxf(m0, fmaxf(s[nt][0], s[nt][1]));
        m1 = fmaxf(m1, fmaxf(s[nt][2], s[nt][3]));
    }
    m0 = fmaxf(m0, __shfl_xor_sync(0xffffffffu, m0, 1));
    m0 = fmaxf(m0, __shfl_xor_sync(0xffffffffu, m0, 2));
    m1 = fmaxf(m1, __shfl_xor_sync(0xffffffffu, m1, 1));
    m1 = fmaxf(m1, __shfl_xor_sync(0xffffffffu, m1, 2));
    float s0 = 0.f, s1 = 0.f;
    #pragma unroll
    for (int nt = 0; nt < 8; nt++){
        s[nt][0] = __expf(s[nt][0]-m0); s[nt][1] = __expf(s[nt][1]-m0);
        s[nt][2] = __expf(s[nt][2]-m1); s[nt][3] = __expf(s[nt][3]-m1);
        s0 += s[nt][0] + s[nt][1];
        s1 += s[nt][2] + s[nt][3];
    }
    s0 += __shfl_xor_sync(0xffffffffu, s0, 1);
    s0 += __shfl_xor_sync(0xffffffffu, s0, 2);
    s1 += __shfl_xor_sync(0xffffffffu, s1, 1);
    s1 += __shfl_xor_sync(0xffffffffu, s1, 2);

    float o[4][4] = {};
    #pragma unroll
    for (int sp = 0; sp < 4; sp++){
        uint32_t a0 = packbf(s[2*sp][0],   s[2*sp][1]);
        uint32_t a1 = packbf(s[2*sp][2],   s[2*sp][3]);
        uint32_t a2 = packbf(s[2*sp+1][0], s[2*sp+1][1]);
        uint32_t a3 = packbf(s[2*sp+1][2], s[2*sp+1][3]);
        #pragma unroll
        for (int nd = 0; nd < 4; nd++){
            const uint32_t* vr = vt + (h*32 + nd*8 + lg)*AV_S + sp*8 + lr;
            mma_bf16(o[nd], a0, a1, a2, a3, vr[0], vr[4]);
        }
    }
    float i0 = 1.f/s0, i1 = 1.f/s1;
    {
        int lrow = wh*8 + (r0>>3), lcol = ww*8 + (r0&7);
        uint32_t* op = ao + ((size_t)b*LL + (size_t)lrow*Wd + lcol)*96 + (h0+h)*16;
        #pragma unroll
        for (int nd = 0; nd < 4; nd++)
            op[nd*4 + lr] = packbf(o[nd][0]*i0, o[nd][1]*i0);
    }
    {
        int lrow = wh*8 + (r1>>3), lcol = ww*8 + (r1&7);
        uint32_t* op = ao + ((size_t)b*LL + (size_t)lrow*Wd + lcol)*96 + (h0+h)*16;
        #pragma unroll
        for (int nd = 0; nd < 4; nd++)
            op[nd*4 + lr] = packbf(o[nd][2]*i1, o[nd][3]*i1);
    }
}

// ---------------- depthwise 3x3 conv: 2 channels (1 word) x 4 pixels per thread ----------------
// in/out: packed bf16 words, token-major, Cw words per token.
__global__ void dwconv4w(const uint32_t* __restrict__ in, const float* __restrict__ w9,
                         uint32_t* __restrict__ out, int Cw, int doGelu){
    long long idx = (long long)blockIdx.x*blockDim.x + threadIdx.x;
    long long total = (long long)TOK*Cw/4;
    if (idx >= total) return;
    int cw = (int)(idx % Cw);
    long long t = idx / Cw;
    int xq = (int)(t & 31);
    int y  = (int)((t >> 5) & 127);
    int b  = (int)(t >> 12);
    int x0 = xq*4;
    const uint32_t* base = in + (size_t)b*LL*Cw + cw;
    float r0[3][6], r1[3][6];
#pragma unroll
    for (int ky=0; ky<3; ky++){
        int iy = y + ky - 1;
        bool yok = (unsigned)iy < (unsigned)Hh;
#pragma unroll
        for (int kx=0; kx<6; kx++){
            int ix = x0 + kx - 1;
            bool ok = yok && ((unsigned)ix < (unsigned)Wd);
            if (ok){
                float2 p = unpackbf(base[((size_t)iy*Wd + ix)*Cw]);
                r0[ky][kx] = p.x; r1[ky][kx] = p.y;
            } else {
                r0[ky][kx] = 0.f; r1[ky][kx] = 0.f;
            }
        }
    }
    float wv0[9], wv1[9];
    const float* wp0 = w9 + (2*cw)*9;
#pragma unroll
    for (int k=0;k<9;k++){ wv0[k] = wp0[k]; wv1[k] = wp0[9+k]; }
    uint32_t* ob = out + ((size_t)b*LL + (size_t)y*Wd + x0)*Cw + cw;
#pragma unroll
    for (int xo=0; xo<4; xo++){
        float a0 = 0.f, a1 = 0.f;
#pragma unroll
        for (int ky=0;ky<3;ky++)
#pragma unroll
            for (int kx=0;kx<3;kx++){
                a0 += r0[ky][xo+kx]*wv0[ky*3+kx];
                a1 += r1[ky][xo+kx]*wv1[ky*3+kx];
            }
        if (doGelu){ a0 = gelu_f(a0); a1 = gelu_f(a1); }
        ob[(size_t)xo*Cw] = packbf(a0, a1);
    }
}

// ---------------- deterministic pooling + channel gate (bf16 conv in) ----------------
__global__ void pool_partial(const __nv_bfloat16* __restrict__ conv, float* __restrict__ pp){
    int b = blockIdx.y, chunk = blockIdx.x, c = threadIdx.x;
    const __nv_bfloat16* p = conv + ((size_t)b*LL + (size_t)chunk*128)*Cc + c;
    float s=0.f;
    for (int r=0;r<128;r++) s += __bfloat162float(p[(size_t)r*Cc]);
    pp[(b*128+chunk)*Cc + c] = s;
}

__global__ void pool_final_cm(const float* __restrict__ pp, const float* __restrict__ w1,
                              const float* __restrict__ w2, float* __restrict__ cm){
    int b = blockIdx.x, c = threadIdx.x;
    __shared__ float ps[Cc];
    __shared__ float ts[REDc];
    float s=0.f;
    for (int r=0;r<128;r++) s += pp[(b*128+r)*Cc + c];
    ps[c] = s*(1.f/(float)LL);
    __syncthreads();
    if (c < REDc){
        float t=0.f;
        for (int j=0;j<Cc;j++) t += ps[j]*w1[c*Cc+j];
        ts[c] = gelu_f(t);
    }
    __syncthreads();
    float a=0.f;
#pragma unroll
    for (int r=0;r<REDc;r++) a += ts[r]*w2[c*REDc+r];
    cm[b*Cc+c] = 1.f/(1.f+__expf(-a));
}

// ---------------- residual + LN2 fused: attn/conv bf16 in, xmid fp32, n2 bf16 ----------------
__global__ void resid_ln2_kernel(const float* __restrict__ x, const uint32_t* __restrict__ attn,
    const uint32_t* __restrict__ conv, const float* __restrict__ cm,
    const float* __restrict__ w, const float* __restrict__ bb,
    float* __restrict__ xmid, uint32_t* __restrict__ n2){
    int warp = (blockIdx.x*blockDim.x + threadIdx.x) >> 5;
    int lane = threadIdx.x & 31;
    if (warp >= TOK) return;
    int b = warp / LL;
    size_t base = (size_t)warp*Cc;
    float v[3][2]; float s=0.f;
#pragma unroll
    for (int k=0;k<3;k++){
        int c2 = lane+32*k;
        int c = 2*c2;
        float2 xv = *(const float2*)&x[base+c];
        float2 av = unpackbf(attn[(size_t)warp*96 + c2]);
        float2 cv = unpackbf(conv[(size_t)warp*96 + c2]);
        float2 gv = *(const float2*)&cm[b*Cc+c];
        float m0 = xv.x + av.x*gv.x + cv.x;
        float m1 = xv.y + av.y*gv.y + cv.y;
        float2 o; o.x=m0; o.y=m1;
        *(float2*)&xmid[base+c] = o;
        v[k][0]=m0; v[k][1]=m1; s+=m0+m1;
    }
#pragma unroll
    for (int o=16;o;o>>=1) s += __shfl_xor_sync(0xffffffffu, s, o);
    float mean = s*(1.f/192.f);
    float q = 0.f;
#pragma unroll
    for (int k=0;k<3;k++){ float d0=v[k][0]-mean, d1=v[k][1]-mean; q += d0*d0 + d1*d1; }
#pragma unroll
    for (int o=16;o;o>>=1) q += __shfl_xor_sync(0xffffffffu, q, o);
    float inv = rsqrtf(q*(1.f/192.f)+1e-5f);
    uint32_t* op = n2 + (size_t)warp*96;
#pragma unroll
    for (int k=0;k<3;k++){
        int c2 = lane+32*k;
        float r0 = (v[k][0]-mean)*inv*w[2*c2]+bb[2*c2];
        float r1 = (v[k][1]-mean)*inv*w[2*c2+1]+bb[2*c2+1];
        op[c2] = packbf(r0, r1);
    }
}

// ---------------- launch ----------------
extern "C" void kernel_launch(void* const* d_in, const int* in_sizes, int n_in,
                              void* d_out, int out_size){
    const float* x     = (const float*)d_in[0];
    const float* n1w   = (const float*)d_in[3];
    const float* n1b   = (const float*)d_in[4];
    const float* qkvw  = (const float*)d_in[5];
    const float* projw = (const float*)d_in[6];
    const float* projb = (const float*)d_in[7];
    const float* abias = (const float*)d_in[8];
    const float* convw = (const float*)d_in[9];
    const float* cgw1  = (const float*)d_in[10];
    const float* cgw2  = (const float*)d_in[11];
    const float* n2w   = (const float*)d_in[12];
    const float* n2b   = (const float*)d_in[13];
    const float* fc1w  = (const float*)d_in[14];
    const float* smixw = (const float*)d_in[15];
    const float* fc2w  = (const float*)d_in[16];
    float* out = (float*)d_out;

    uint32_t *n1p, *aop, *qkvp, *hp, *h2p, *wtp, *attnp, *convp;
    float *ppp, *cmp;
    cudaGetSymbolAddress((void**)&n1p,   g_n1);
    cudaGetSymbolAddress((void**)&aop,   g_ao);
    cudaGetSymbolAddress((void**)&qkvp,  g_qkv);
    cudaGetSymbolAddress((void**)&hp,    g_h);
    cudaGetSymbolAddress((void**)&h2p,   g_h2);
    cudaGetSymbolAddress((void**)&wtp,   g_wt);
    cudaGetSymbolAddress((void**)&attnp, g_attn);
    cudaGetSymbolAddress((void**)&convp, g_conv);
    cudaGetSymbolAddress((void**)&ppp,   g_poolp);
    cudaGetSymbolAddress((void**)&cmp,   g_cm);

    cudaFuncSetAttribute(gemm_mma, cudaFuncAttributeMaxDynamicSharedMemorySize, GEMM_SMEM);

    // 0. weight transposes -> bf16 (tiny)
    transpose_all<<<576, 256>>>(qkvw, projw, fc1w, fc2w, wtp);
    // 1. n1 = LN1(x) -> bf16
    ln_kernel<<<TOK/8, 256>>>(x, n1w, n1b, n1p);
    // 2. qkv = n1 @ qkv_w -> bf16
    gemm_mma<<<dim3(QKVN/64, TOK/256), 256, GEMM_SMEM>>>(n1p, wtp+WTB_QKV, qkvp, nullptr, QKVN, Cc, 4);
    // 3. attention -> ao (bf16)
    attn_mma<<<dim3(2048, 3), 256>>>(qkvp, abias, aop);
    // 4. attn_feat = ao @ proj_w + proj_b -> bf16
    gemm_mma<<<dim3(Cc/64, TOK/256), 256, GEMM_SMEM>>>(aop, wtp+WTB_PROJ, attnp, projb, Cc, Cc, 6);
    // 5. conv_feat = gelu(dwconv(n1)) -> bf16
    dwconv4w<<<(TOK*96/4 + 255)/256, 256>>>(n1p, convw, convp, 96, 1);
    // 6. channel gate
    pool_partial<<<dim3(128, Bsz), Cc>>>((const __nv_bfloat16*)convp, ppp);
    pool_final_cm<<<Bsz, Cc>>>(ppp, cgw1, cgw2, cmp);
    // 7. xmid -> out (fp32) ; n2 -> g_n1 (bf16, reuse)
    resid_ln2_kernel<<<TOK/8, 256>>>(x, attnp, convp, cmp, n2w, n2b, out, n1p);
    // 8. h = gelu(n2 @ fc1_w) -> bf16
    gemm_mma<<<dim3(HDIMc/64, TOK/256), 256, GEMM_SMEM>>>(n1p, wtp+WTB_FC1, hp, nullptr, HDIMc, Cc, 5);
    // 9. h2 = dwconv(h) -> bf16 (no gelu)
    dwconv4w<<<(TOK*192/4 + 255)/256, 256>>>(hp, smixw, h2p, 192, 0);
    // 10. out = xmid + h2 @ fc2_w (fp32 residual in-place)
    gemm_mma<<<dim3(Cc/64, TOK/256), 256, GEMM_SMEM>>>(h2p, wtp+WTB_FC2, out, out, Cc, HDIMc, 3);
}